// round 3
// baseline (speedup 1.0000x reference)
#include <cuda_runtime.h>
#include <math.h>

#define BB 32
#define TT 63
#define TIN_ 64
#define DD 1024
#define EE 256
#define VV 32000
#define KZ 2304      // (E+D) + D
#define NZ 4096      // 4*D
#define KA 2048      // 2*D
#define MROWS 2016   // T*B
#define MPAD 2048
#define NSPLIT 8

// ---- persistent scratch (static __device__, no allocation) ----
__device__ __align__(128) float g_h[BB*DD];
__device__ __align__(128) float g_c[BB*DD];
__device__ __align__(128) float g_ctx[BB*DD];
__device__ __align__(128) float g_attn0[BB*DD];          // zeros (attention carry at t=0)
__device__ __align__(128) float g_keys[BB*TIN_*DD];
__device__ __align__(128) float g_attnAll[MPAD*DD];      // row (t*32+b); tail rows zeroed
__device__ __align__(128) float g_zpart[NSPLIT*BB*NZ];   // split-K partials for z
__device__ __align__(128) float g_apart[NSPLIT*BB*DD];   // split-K partials for attn_new

// Blackwell packed fp32x2 FMA (SASS FFMA2)
__device__ __forceinline__ unsigned long long fma2(unsigned long long a,
                                                   unsigned long long b,
                                                   unsigned long long c) {
    unsigned long long d;
    asm("fma.rn.f32x2 %0, %1, %2, %3;" : "=l"(d) : "l"(a), "l"(b), "l"(c));
    return d;
}

__device__ __forceinline__ float sigm(float x) { return 1.f / (1.f + expf(-x)); }

// ---- init: load recurrent state, zero attn carry and attnAll tail ----
__global__ void init_kernel(const float* __restrict__ h0, const float* __restrict__ c0) {
    int i = blockIdx.x * blockDim.x + threadIdx.x;   // 0..32767
    g_h[i] = h0[i];
    g_c[i] = c0[i];
    g_attn0[i] = 0.f;
    g_attnAll[MROWS*DD + i] = 0.f;                   // pad rows
}

// ---- big GEMM: MODE 0 = keys (memory@Wm -> g_keys), MODE 1 = logits (g_attnAll@Wfc+bfc -> out) ----
// 128x128 tile, BK=16, 256 threads, 8m x 8n per thread via f32x2 with duplicated A in shared.
template<int MODE>
__global__ __launch_bounds__(256)
void gemm_big(const float* __restrict__ Aext, const float* __restrict__ Bw,
              const float* __restrict__ bias, float* __restrict__ Cext,
              int M, int N, int K)
{
    __shared__ float2 As[16][128];   // [k][m], value duplicated (a,a)
    __shared__ float  Bs[16][128];   // [k][n]
    const float* A = (MODE == 0) ? Aext : g_attnAll;

    const int tx = threadIdx.x & 15;
    const int ty = threadIdx.x >> 4;
    const int bm = blockIdx.y * 128;
    const int bn = blockIdx.x * 128;

    unsigned long long acc[8][4];
#pragma unroll
    for (int i = 0; i < 8; i++)
#pragma unroll
        for (int j = 0; j < 4; j++) acc[i][j] = 0ull;

    const int am = threadIdx.x >> 1;            // 0..127
    const int ak = (threadIdx.x & 1) * 8;
    const int bk = threadIdx.x >> 4;            // 0..15
    const int bq = (threadIdx.x & 15) * 8;
    const float* Arow = A + (size_t)(bm + am) * K + ak;
    const float* Bcol = Bw + bn + bq;

    for (int k0 = 0; k0 < K; k0 += 16) {
        float4 a0 = *(const float4*)(Arow + k0);
        float4 a1 = *(const float4*)(Arow + k0 + 4);
        float4 b0 = *(const float4*)(Bcol + (size_t)(k0 + bk) * N);
        float4 b1 = *(const float4*)(Bcol + (size_t)(k0 + bk) * N + 4);
        __syncthreads();
        As[ak+0][am] = make_float2(a0.x, a0.x);
        As[ak+1][am] = make_float2(a0.y, a0.y);
        As[ak+2][am] = make_float2(a0.z, a0.z);
        As[ak+3][am] = make_float2(a0.w, a0.w);
        As[ak+4][am] = make_float2(a1.x, a1.x);
        As[ak+5][am] = make_float2(a1.y, a1.y);
        As[ak+6][am] = make_float2(a1.z, a1.z);
        As[ak+7][am] = make_float2(a1.w, a1.w);
        *(float4*)&Bs[bk][bq]     = b0;
        *(float4*)&Bs[bk][bq + 4] = b1;
        __syncthreads();
#pragma unroll
        for (int kk = 0; kk < 16; kk++) {
            unsigned long long av[8], bv[4];
#pragma unroll
            for (int i = 0; i < 8; i++)
                av[i] = *reinterpret_cast<const unsigned long long*>(&As[kk][ty*8 + i]);
#pragma unroll
            for (int j = 0; j < 4; j++)
                bv[j] = *reinterpret_cast<const unsigned long long*>(&Bs[kk][tx*2 + 32*j]);
#pragma unroll
            for (int i = 0; i < 8; i++)
#pragma unroll
                for (int j = 0; j < 4; j++)
                    acc[i][j] = fma2(av[i], bv[j], acc[i][j]);
        }
    }

#pragma unroll
    for (int i = 0; i < 8; i++) {
        int m = bm + ty*8 + i;
        if (MODE == 1 && m >= MROWS) continue;
#pragma unroll
        for (int j = 0; j < 4; j++) {
            int n = bn + tx*2 + 32*j;
            float2 v = *reinterpret_cast<float2*>(&acc[i][j]);
            if (MODE == 1) {
                v.x += bias[n];
                v.y += bias[n + 1];
                int tt = m >> 5, bb = m & 31;                  // row = t*32 + b
                *(float2*)&Cext[((size_t)bb * TT + tt) * VV + n] = v;
            } else {
                *(float2*)&g_keys[(size_t)m * N + n] = v;
            }
        }
    }
}

// ---- small-M GEMM with split-K and fused A-gather ----
// MODE 0: z = [emb(tok), attn_prev] @ Wx + h @ Wh   (K=2304, N=4096) -> g_zpart
// MODE 1: attn partial = [h_new, ctx] @ Wa          (K=2048, N=1024) -> g_apart
// 32x128 tile, BK=32, 256 threads, 4m x 2(n-f32x2) per thread.
template<int MODE>
__global__ __launch_bounds__(256)
void gemm_small(const float* __restrict__ emb, const int* __restrict__ ids,
                const float* __restrict__ Wx, const float* __restrict__ Wh,
                const float* __restrict__ Wa, int t)
{
    const int KSP  = (MODE == 0) ? (KZ / NSPLIT) : (KA / NSPLIT);  // 288 / 256
    const int NTOT = (MODE == 0) ? NZ : DD;
    __shared__ float2 As[32][33];    // [k][b] duplicated, padded
    __shared__ float  Bs[32][128];

    const int s  = blockIdx.z;
    const int bn = blockIdx.x * 128;
    const int kb = s * KSP;
    const int nx = threadIdx.x & 31, my = threadIdx.x >> 5;
    const int am = threadIdx.x >> 3;            // 0..31 (batch row)
    const int ak = (threadIdx.x & 7) * 4;
    const int bk = threadIdx.x >> 3;            // 0..31
    const int bq = (threadIdx.x & 7) * 16;
    const float* attn_prev = (t == 0) ? g_attn0 : (g_attnAll + (size_t)(t - 1) * BB * DD);

    unsigned long long acc[4][2];
#pragma unroll
    for (int i = 0; i < 4; i++)
#pragma unroll
        for (int j = 0; j < 2; j++) acc[i][j] = 0ull;

    for (int k0 = 0; k0 < KSP; k0 += 32) {
        int kg = kb + k0 + ak;
        float4 a;
        if (MODE == 0) {
            if (kg < EE)          a = *(const float4*)(emb + (size_t)ids[am*TT + t]*EE + kg);
            else if (kg < EE+DD)  a = *(const float4*)(attn_prev + am*DD + (kg - EE));
            else                  a = *(const float4*)(g_h + am*DD + (kg - EE - DD));
        } else {
            if (kg < DD) a = *(const float4*)(g_h + am*DD + kg);
            else         a = *(const float4*)(g_ctx + am*DD + (kg - DD));
        }
        int kr = kb + k0 + bk;
        const float* brow;
        if (MODE == 0) brow = (kr < EE+DD) ? (Wx + (size_t)kr * NZ)
                                           : (Wh + (size_t)(kr - EE - DD) * NZ);
        else           brow = Wa + (size_t)kr * DD;
        float4 b0 = *(const float4*)(brow + bn + bq);
        float4 b1 = *(const float4*)(brow + bn + bq + 4);
        float4 b2 = *(const float4*)(brow + bn + bq + 8);
        float4 b3 = *(const float4*)(brow + bn + bq + 12);
        __syncthreads();
        As[ak+0][am] = make_float2(a.x, a.x);
        As[ak+1][am] = make_float2(a.y, a.y);
        As[ak+2][am] = make_float2(a.z, a.z);
        As[ak+3][am] = make_float2(a.w, a.w);
        *(float4*)&Bs[bk][bq]      = b0;
        *(float4*)&Bs[bk][bq + 4]  = b1;
        *(float4*)&Bs[bk][bq + 8]  = b2;
        *(float4*)&Bs[bk][bq + 12] = b3;
        __syncthreads();
#pragma unroll
        for (int kk = 0; kk < 32; kk++) {
            unsigned long long av[4], bv[2];
#pragma unroll
            for (int i = 0; i < 4; i++)
                av[i] = *reinterpret_cast<const unsigned long long*>(&As[kk][my*4 + i]);
#pragma unroll
            for (int j = 0; j < 2; j++)
                bv[j] = *reinterpret_cast<const unsigned long long*>(&Bs[kk][nx*2 + 64*j]);
#pragma unroll
            for (int i = 0; i < 4; i++)
#pragma unroll
                for (int j = 0; j < 2; j++)
                    acc[i][j] = fma2(av[i], bv[j], acc[i][j]);
        }
    }

    float* outp = (MODE == 0) ? g_zpart : g_apart;
#pragma unroll
    for (int i = 0; i < 4; i++) {
        int b = my*4 + i;
#pragma unroll
        for (int j = 0; j < 2; j++) {
            int n = bn + nx*2 + 64*j;
            *(float2*)&outp[(size_t)(s*BB + b) * NTOT + n] =
                *reinterpret_cast<float2*>(&acc[i][j]);
        }
    }
}

// ---- per-step: combine z partials, LSTM gates, scores + softmax + context ----
__global__ __launch_bounds__(256)
void step_attn(const float* __restrict__ b4, const float* __restrict__ memory,
               const float* __restrict__ scale)
{
    __shared__ float h_s[DD];
    __shared__ float sc[TIN_];
    __shared__ float inv_s;
    const int b = blockIdx.x, tid = threadIdx.x;
    const int j0 = tid * 4;

    float zi[4], zf[4], zg[4], zo[4];
#pragma unroll
    for (int r = 0; r < 4; r++) {
        zi[r] = b4[j0 + r];
        zf[r] = b4[DD + j0 + r];
        zg[r] = b4[2*DD + j0 + r];
        zo[r] = b4[3*DD + j0 + r];
    }
#pragma unroll
    for (int s = 0; s < NSPLIT; s++) {
        const float* zp = g_zpart + (size_t)(s*BB + b) * NZ;
#pragma unroll
        for (int r = 0; r < 4; r++) {
            zi[r] += zp[j0 + r];
            zf[r] += zp[DD + j0 + r];
            zg[r] += zp[2*DD + j0 + r];
            zo[r] += zp[3*DD + j0 + r];
        }
    }
#pragma unroll
    for (int r = 0; r < 4; r++) {
        float cn = sigm(zf[r]) * g_c[b*DD + j0 + r] + sigm(zi[r]) * tanhf(zg[r]);
        float hn = sigm(zo[r]) * tanhf(cn);
        g_c[b*DD + j0 + r] = cn;
        g_h[b*DD + j0 + r] = hn;
        h_s[j0 + r] = hn;
    }
    __syncthreads();

    // scores: 8 warps x 8 positions
    const int w = tid >> 5, lane = tid & 31;
#pragma unroll
    for (int p = 0; p < 8; p++) {
        int pos = w*8 + p;
        const float* kr = g_keys + ((size_t)b*TIN_ + pos) * DD;
        float sacc = 0.f;
        for (int d = lane; d < DD; d += 32) sacc += h_s[d] * kr[d];
#pragma unroll
        for (int off = 16; off > 0; off >>= 1)
            sacc += __shfl_xor_sync(0xffffffffu, sacc, off);
        if (lane == 0) sc[pos] = sacc * scale[0];
    }
    __syncthreads();

    // softmax over 64 (warp 0)
    if (tid < 32) {
        float a = sc[tid], c2 = sc[tid + 32];
        float m = fmaxf(a, c2);
#pragma unroll
        for (int off = 16; off > 0; off >>= 1)
            m = fmaxf(m, __shfl_xor_sync(0xffffffffu, m, off));
        float ea = expf(a - m), eb = expf(c2 - m);
        float ssum = ea + eb;
#pragma unroll
        for (int off = 16; off > 0; off >>= 1)
            ssum += __shfl_xor_sync(0xffffffffu, ssum, off);
        sc[tid] = ea;
        sc[tid + 32] = eb;
        if (tid == 0) inv_s = 1.f / ssum;
    }
    __syncthreads();

    const float inv = inv_s;
#pragma unroll
    for (int q = 0; q < 4; q++) {
        int d = tid + q * 256;
        float acc = 0.f;
#pragma unroll 8
        for (int tt = 0; tt < TIN_; tt++)
            acc += sc[tt] * memory[((size_t)b*TIN_ + tt) * DD + d];
        g_ctx[b*DD + d] = acc * inv;
    }
}

// ---- combine attn split-K partials into g_attnAll row block t ----
__global__ __launch_bounds__(256)
void combine_attn(int t) {
    int i = blockIdx.x * blockDim.x + threadIdx.x;   // 0..32767
    float a = 0.f;
#pragma unroll
    for (int s = 0; s < NSPLIT; s++) a += g_apart[s*BB*DD + i];
    g_attnAll[(size_t)t * BB * DD + i] = a;
}

extern "C" void kernel_launch(void* const* d_in, const int* in_sizes, int n_in,
                              void* d_out, int out_size) {
    const int*   ids    = (const int*)  d_in[0];
    const float* h0     = (const float*)d_in[1];
    const float* c0     = (const float*)d_in[2];
    const float* memory = (const float*)d_in[3];
    const float* emb    = (const float*)d_in[4];
    const float* Wx     = (const float*)d_in[5];
    const float* Wh     = (const float*)d_in[6];
    const float* b4     = (const float*)d_in[7];
    const float* Wm     = (const float*)d_in[8];
    const float* scale  = (const float*)d_in[9];
    const float* Wa     = (const float*)d_in[10];
    const float* Wfc    = (const float*)d_in[11];
    const float* bfc    = (const float*)d_in[12];
    float* out = (float*)d_out;

    init_kernel<<<128, 256>>>(h0, c0);

    {   // keys = memory @ Wm : [2048,1024]x[1024,1024]
        dim3 g(8, 16);
        gemm_big<0><<<g, 256>>>(memory, Wm, nullptr, nullptr, 2048, 1024, 1024);
    }

    for (int t = 0; t < TT; t++) {
        {   dim3 g(NZ/128, 1, NSPLIT);      // 32 x 8
            gemm_small<0><<<g, 256>>>(emb, ids, Wx, Wh, nullptr, t);
        }
        step_attn<<<BB, 256>>>(b4, memory, scale);
        {   dim3 g(DD/128, 1, NSPLIT);      // 8 x 8
            gemm_small<1><<<g, 256>>>(emb, ids, nullptr, nullptr, Wa, t);
        }
        combine_attn<<<128, 256>>>(t);
    }

    {   // logits = attnAll @ Wfc + bfc : [2048,1024]x[1024,32000]
        dim3 g(VV/128, MPAD/128);           // 250 x 16
        gemm_big<1><<<g, 256>>>(nullptr, Wfc, bfc, out, MPAD, VV, 1024);
    }
}

// round 4
// speedup vs baseline: 1.1205x; 1.1205x over previous
#include <cuda_runtime.h>
#include <math.h>

#define BB 32
#define TT 63
#define TIN_ 64
#define DD 1024
#define EE 256
#define VV 32000
#define NZ 4096
#define MROWS 2016
#define MPAD 2048
#define NSPLIT 8

// ---- persistent scratch (static __device__, no allocation) ----
__device__ __align__(128) float g_h[BB*DD];
__device__ __align__(128) float g_c[BB*DD];
__device__ __align__(128) float g_zero[BB*DD];
__device__ __align__(128) float g_keys[BB*TIN_*DD];
__device__ __align__(128) float g_attnAll[MPAD*DD];
__device__ __align__(128) float g_zpart[NSPLIT*BB*NZ];
__device__ __align__(128) float g_embW[MPAD*NZ];      // emb[ids]@Wx_emb per (t,b)
__device__ __align__(128) float g_Wz[2*DD*NZ];        // [WhC ; Wcomb_bot]
__device__ __align__(128) float g_hHist[MPAD*DD];
__device__ __align__(128) float g_ctxHist[MPAD*DD];

// Blackwell packed fp32x2 FMA (SASS FFMA2)
__device__ __forceinline__ unsigned long long fma2(unsigned long long a,
                                                   unsigned long long b,
                                                   unsigned long long c) {
    unsigned long long d;
    asm("fma.rn.f32x2 %0, %1, %2, %3;" : "=l"(d) : "l"(a), "l"(b), "l"(c));
    return d;
}
__device__ __forceinline__ float sigm(float x) { return 1.f / (1.f + expf(-x)); }

__global__ void init_kernel(const float* __restrict__ h0, const float* __restrict__ c0) {
    int i = blockIdx.x * blockDim.x + threadIdx.x;   // 0..32767
    g_h[i] = h0[i];
    g_c[i] = c0[i];
    g_zero[i] = 0.f;
}

// ============================================================================
// gemm_big: 128x128 tile, BK=16, 256 thr, 8m x 4(f32x2 n) per thread, double-buffered.
// MODE 0: keys   = memory @ Wm            -> g_keys              (N=1024,K=1024)
// MODE 1: logits = g_attnAll @ Wfc + bfc  -> out (permuted)      (N=32000,K=1024)
// MODE 2: Wz     = Wa @ Wx_attn (+Wh top) -> g_Wz                (N=4096,K=1024)
// MODE 3: embW   = emb[ids] @ Wx_emb      -> g_embW              (N=4096,K=256)
// MODE 4: attn   = [hHist,ctxHist] @ Wa   -> g_attnAll (0 pads)  (N=1024,K=2048)
// ============================================================================
template<int MODE>
__global__ __launch_bounds__(256, 2)
void gemm_big(const float* __restrict__ Aext, const float* __restrict__ Bw,
              const float* __restrict__ aux, float* __restrict__ Cext,
              const int* __restrict__ ids, const float* __restrict__ emb,
              int N, int K)
{
    __shared__ float2 As[2][16][128];
    __shared__ float  Bs[2][16][128];

    const int tx = threadIdx.x & 15, ty = threadIdx.x >> 4;
    const int bm = blockIdx.y * 128, bn = blockIdx.x * 128;
    const int am = threadIdx.x >> 1, ak = (threadIdx.x & 1) * 8;
    const int bk = threadIdx.x >> 4, bq = (threadIdx.x & 15) * 8;
    const int m  = bm + am;

    const float* Arow = nullptr;
    if (MODE == 0 || MODE == 2) Arow = Aext + (size_t)m * K + ak;
    else if (MODE == 1)         Arow = g_attnAll + (size_t)m * K + ak;
    else if (MODE == 3) {
        int mm = (m < MROWS) ? m : (MROWS - 1);
        Arow = emb + (size_t)ids[(mm & 31) * TT + (mm >> 5)] * EE + ak;
    }
    const float* Bcol = Bw + bn + bq;

    unsigned long long acc[8][4];
#pragma unroll
    for (int i = 0; i < 8; i++)
#pragma unroll
        for (int j = 0; j < 4; j++) acc[i][j] = 0ull;

    float4 a0, a1, b0, b1;

#define GB_LOAD(K0)                                                            \
    {                                                                          \
        if (MODE == 4) {                                                       \
            if (m >= MROWS) { a0 = make_float4(0,0,0,0); a1 = a0; }            \
            else {                                                             \
                int kg = (K0) + ak;                                            \
                const float* p = (kg < DD)                                     \
                    ? (g_hHist   + (size_t)m * DD + kg)                        \
                    : (g_ctxHist + (size_t)m * DD + (kg - DD));                \
                a0 = *(const float4*)p; a1 = *(const float4*)(p + 4);          \
            }                                                                  \
        } else {                                                               \
            a0 = *(const float4*)(Arow + (K0));                                \
            a1 = *(const float4*)(Arow + (K0) + 4);                            \
        }                                                                      \
        b0 = *(const float4*)(Bcol + (size_t)((K0) + bk) * N);                 \
        b1 = *(const float4*)(Bcol + (size_t)((K0) + bk) * N + 4);             \
    }

#define GB_STORE(BUF)                                                          \
    {                                                                          \
        As[BUF][ak+0][am] = make_float2(a0.x, a0.x);                           \
        As[BUF][ak+1][am] = make_float2(a0.y, a0.y);                           \
        As[BUF][ak+2][am] = make_float2(a0.z, a0.z);                           \
        As[BUF][ak+3][am] = make_float2(a0.w, a0.w);                           \
        As[BUF][ak+4][am] = make_float2(a1.x, a1.x);                           \
        As[BUF][ak+5][am] = make_float2(a1.y, a1.y);                           \
        As[BUF][ak+6][am] = make_float2(a1.z, a1.z);                           \
        As[BUF][ak+7][am] = make_float2(a1.w, a1.w);                           \
        *(float4*)&Bs[BUF][bk][bq]     = b0;                                   \
        *(float4*)&Bs[BUF][bk][bq + 4] = b1;                                   \
    }

    const int NT = K / 16;
    GB_LOAD(0)
    GB_STORE(0)
    __syncthreads();

    for (int tile = 0; tile < NT; tile++) {
        int cur = tile & 1;
        if (tile + 1 < NT) GB_LOAD((tile + 1) * 16)
#pragma unroll
        for (int kk = 0; kk < 16; kk++) {
            unsigned long long av[8], bv[4];
#pragma unroll
            for (int i = 0; i < 8; i++)
                av[i] = *reinterpret_cast<const unsigned long long*>(&As[cur][kk][ty*8 + i]);
#pragma unroll
            for (int j = 0; j < 4; j++)
                bv[j] = *reinterpret_cast<const unsigned long long*>(&Bs[cur][kk][tx*2 + 32*j]);
#pragma unroll
            for (int i = 0; i < 8; i++)
#pragma unroll
                for (int j = 0; j < 4; j++)
                    acc[i][j] = fma2(av[i], bv[j], acc[i][j]);
        }
        if (tile + 1 < NT) { GB_STORE(cur ^ 1) __syncthreads(); }
    }
#undef GB_LOAD
#undef GB_STORE

#pragma unroll
    for (int i = 0; i < 8; i++) {
        int mo = bm + ty*8 + i;
        if (MODE == 1 && mo >= MROWS) continue;
#pragma unroll
        for (int j = 0; j < 4; j++) {
            int n = bn + tx*2 + 32*j;
            float2 v = *reinterpret_cast<float2*>(&acc[i][j]);
            if (MODE == 0) {
                *(float2*)&g_keys[(size_t)mo * DD + n] = v;
            } else if (MODE == 1) {
                v.x += aux[n]; v.y += aux[n + 1];
                int tt3 = mo >> 5, bb = mo & 31;
                *(float2*)&Cext[((size_t)bb * TT + tt3) * VV + n] = v;
            } else if (MODE == 2) {
                if (mo < DD) { v.x += aux[(size_t)mo*NZ + n]; v.y += aux[(size_t)mo*NZ + n + 1]; }
                *(float2*)&g_Wz[(size_t)mo * NZ + n] = v;
            } else if (MODE == 3) {
                *(float2*)&g_embW[(size_t)mo * NZ + n] = v;
            } else {
                *(float2*)&g_attnAll[(size_t)mo * DD + n] = v;
            }
        }
    }
}

// ============================================================================
// zstep_gemm: z partials = [h ; ctx_prev] @ [Btop ; Wcomb_bot]
// M=32, N=4096, K=2048 split 8 (KSP=256), BK=16, 256 thr, double-buffered.
// ============================================================================
__global__ __launch_bounds__(256)
void zstep_gemm(const float* __restrict__ Wh, int t)
{
    __shared__ float2 As[2][16][33];
    __shared__ float  Bs[2][16][128];

    const float* Btop    = (t == 0) ? Wh : g_Wz;
    const float* Bbot    = g_Wz + (size_t)DD * NZ;
    const float* ctxprev = (t == 0) ? g_zero : (g_ctxHist + (size_t)(t - 1) * BB * DD);

    const int s  = blockIdx.z;
    const int bn = blockIdx.x * 128;
    const int kb = s * 256;
    const int nx = threadIdx.x & 31, my = threadIdx.x >> 5;
    const int am = threadIdx.x >> 3, ak = (threadIdx.x & 7) * 2;   // A: float2
    const int bk = threadIdx.x >> 4, bq = (threadIdx.x & 15) * 8;  // B: 2x float4

    unsigned long long acc[4][2];
#pragma unroll
    for (int i = 0; i < 4; i++)
#pragma unroll
        for (int j = 0; j < 2; j++) acc[i][j] = 0ull;

    float2 a; float4 b0, b1;

#define ZS_LOAD(K0)                                                            \
    {                                                                          \
        int kg = kb + (K0) + ak;                                               \
        const float* ap = (kg < DD) ? (g_h + am*DD + kg)                       \
                                    : (ctxprev + am*DD + (kg - DD));           \
        a = *(const float2*)ap;                                                \
        int kr = kb + (K0) + bk;                                               \
        const float* brow = (kr < DD) ? (Btop + (size_t)kr * NZ)               \
                                      : (Bbot + (size_t)(kr - DD) * NZ);       \
        b0 = *(const float4*)(brow + bn + bq);                                 \
        b1 = *(const float4*)(brow + bn + bq + 4);                             \
    }

#define ZS_STORE(BUF)                                                          \
    {                                                                          \
        As[BUF][ak+0][am] = make_float2(a.x, a.x);                             \
        As[BUF][ak+1][am] = make_float2(a.y, a.y);                             \
        *(float4*)&Bs[BUF][bk][bq]     = b0;                                   \
        *(float4*)&Bs[BUF][bk][bq + 4] = b1;                                   \
    }

    const int NT = 256 / 16;   // 16 tiles
    ZS_LOAD(0)
    ZS_STORE(0)
    __syncthreads();

    for (int tile = 0; tile < NT; tile++) {
        int cur = tile & 1;
        if (tile + 1 < NT) ZS_LOAD((tile + 1) * 16)
#pragma unroll
        for (int kk = 0; kk < 16; kk++) {
            unsigned long long av[4], bv[2];
#pragma unroll
            for (int i = 0; i < 4; i++)
                av[i] = *reinterpret_cast<const unsigned long long*>(&As[cur][kk][my*4 + i]);
#pragma unroll
            for (int j = 0; j < 2; j++)
                bv[j] = *reinterpret_cast<const unsigned long long*>(&Bs[cur][kk][nx*2 + 64*j]);
#pragma unroll
            for (int i = 0; i < 4; i++)
#pragma unroll
                for (int j = 0; j < 2; j++)
                    acc[i][j] = fma2(av[i], bv[j], acc[i][j]);
        }
        if (tile + 1 < NT) { ZS_STORE(cur ^ 1) __syncthreads(); }
    }
#undef ZS_LOAD
#undef ZS_STORE

#pragma unroll
    for (int i = 0; i < 4; i++) {
        int b = my*4 + i;
#pragma unroll
        for (int j = 0; j < 2; j++) {
            int n = bn + nx*2 + 64*j;
            *(float2*)&g_zpart[(size_t)(s*BB + b) * NZ + n] =
                *reinterpret_cast<float2*>(&acc[i][j]);
        }
    }
}

// ============================================================================
// step_fused: z-combine + LSTM gates + scores + softmax + context. One CTA per b.
// ============================================================================
#define ACC2(v, p) { float2 _t = *(const float2*)(p); v.x += _t.x; v.y += _t.y; }

__global__ __launch_bounds__(512)
void step_fused(const float* __restrict__ b4, const float* __restrict__ scale,
                const float* __restrict__ memory, int t)
{
    __shared__ __align__(16) float h_s[DD];
    __shared__ float sc[TIN_];
    __shared__ float al_s[TIN_];
    const int b = blockIdx.x, tid = threadIdx.x;
    const int j0 = tid * 2;

    // ---- gates ----
    float2 zi = *(const float2*)(b4 + j0);
    float2 zf = *(const float2*)(b4 + DD + j0);
    float2 zg = *(const float2*)(b4 + 2*DD + j0);
    float2 zo = *(const float2*)(b4 + 3*DD + j0);
    const float* ew = g_embW + ((size_t)t*BB + b) * NZ;
    ACC2(zi, ew + j0); ACC2(zf, ew + DD + j0); ACC2(zg, ew + 2*DD + j0); ACC2(zo, ew + 3*DD + j0);
#pragma unroll
    for (int s = 0; s < NSPLIT; s++) {
        const float* zp = g_zpart + (size_t)(s*BB + b) * NZ;
        ACC2(zi, zp + j0); ACC2(zf, zp + DD + j0);
        ACC2(zg, zp + 2*DD + j0); ACC2(zo, zp + 3*DD + j0);
    }
    float2 c = *(const float2*)(g_c + b*DD + j0);
    float2 cn, hn;
    cn.x = sigm(zf.x) * c.x + sigm(zi.x) * tanhf(zg.x);
    cn.y = sigm(zf.y) * c.y + sigm(zi.y) * tanhf(zg.y);
    hn.x = sigm(zo.x) * tanhf(cn.x);
    hn.y = sigm(zo.y) * tanhf(cn.y);
    *(float2*)(g_c + b*DD + j0) = cn;
    *(float2*)(g_h + b*DD + j0) = hn;
    *(float2*)(g_hHist + ((size_t)t*BB + b)*DD + j0) = hn;
    *(float2*)(h_s + j0) = hn;
    __syncthreads();

    // ---- scores: 16 warps x 4 positions, h cached in registers ----
    const int w = tid >> 5, lane = tid & 31;
    const float4* hv4 = (const float4*)h_s;
    float4 hreg[8];
#pragma unroll
    for (int it = 0; it < 8; it++) hreg[it] = hv4[it*32 + lane];
    const float sc0 = scale[0];
    float pa[4] = {0.f, 0.f, 0.f, 0.f};
#pragma unroll
    for (int p = 0; p < 4; p++) {
        const float4* kr = (const float4*)(g_keys + ((size_t)b*TIN_ + w*4 + p) * DD);
#pragma unroll
        for (int it = 0; it < 8; it++) {
            float4 kv = kr[it*32 + lane];
            pa[p] += kv.x*hreg[it].x + kv.y*hreg[it].y + kv.z*hreg[it].z + kv.w*hreg[it].w;
        }
    }
#pragma unroll
    for (int p = 0; p < 4; p++) {
        float v = pa[p];
#pragma unroll
        for (int off = 16; off > 0; off >>= 1)
            v += __shfl_xor_sync(0xffffffffu, v, off);
        if (lane == 0) sc[w*4 + p] = v * sc0;
    }
    __syncthreads();

    // ---- softmax over 64 (warp 0) ----
    if (tid < 32) {
        float a = sc[tid], c2 = sc[tid + 32];
        float mx = fmaxf(a, c2);
#pragma unroll
        for (int off = 16; off > 0; off >>= 1)
            mx = fmaxf(mx, __shfl_xor_sync(0xffffffffu, mx, off));
        float ea = expf(a - mx), eb = expf(c2 - mx);
        float ssum = ea + eb;
#pragma unroll
        for (int off = 16; off > 0; off >>= 1)
            ssum += __shfl_xor_sync(0xffffffffu, ssum, off);
        float inv = 1.f / ssum;
        al_s[tid] = ea * inv;
        al_s[tid + 32] = eb * inv;
    }
    __syncthreads();

    // ---- context ----
    const float* mb = memory + (size_t)b * TIN_ * DD;
    float* ch = g_ctxHist + ((size_t)t*BB + b) * DD;
#pragma unroll
    for (int q = 0; q < 2; q++) {
        int d = tid + q * 512;
        float acc = 0.f;
#pragma unroll 8
        for (int tt2 = 0; tt2 < TIN_; tt2++)
            acc += al_s[tt2] * mb[(size_t)tt2 * DD + d];
        ch[d] = acc;
    }
}

extern "C" void kernel_launch(void* const* d_in, const int* in_sizes, int n_in,
                              void* d_out, int out_size) {
    const int*   ids    = (const int*)  d_in[0];
    const float* h0     = (const float*)d_in[1];
    const float* c0     = (const float*)d_in[2];
    const float* memory = (const float*)d_in[3];
    const float* emb    = (const float*)d_in[4];
    const float* Wx     = (const float*)d_in[5];
    const float* Wh     = (const float*)d_in[6];
    const float* b4     = (const float*)d_in[7];
    const float* Wm     = (const float*)d_in[8];
    const float* scale  = (const float*)d_in[9];
    const float* Wa     = (const float*)d_in[10];
    const float* Wfc    = (const float*)d_in[11];
    const float* bfc    = (const float*)d_in[12];
    float* out = (float*)d_out;

    init_kernel<<<128, 256>>>(h0, c0);

    // keys = memory @ Wm
    gemm_big<0><<<dim3(8, 16), 256>>>(memory, Wm, nullptr, nullptr, ids, emb, 1024, 1024);
    // Wz = [Wh + Wa_h@Wx_attn ; Wa_ctx@Wx_attn]
    gemm_big<2><<<dim3(32, 16), 256>>>(Wa, Wx + 256*4096, Wh, nullptr, ids, emb, 4096, 1024);
    // embW = emb[ids] @ Wx_emb
    gemm_big<3><<<dim3(32, 16), 256>>>(nullptr, Wx, nullptr, nullptr, ids, emb, 4096, 256);

    for (int t = 0; t < TT; t++) {
        zstep_gemm<<<dim3(32, 1, NSPLIT), 256>>>(Wh, t);
        step_fused<<<BB, 512>>>(b4, scale, memory, t);
    }

    // attnAll = [hHist, ctxHist] @ Wa
    gemm_big<4><<<dim3(8, 16), 256>>>(nullptr, Wa, nullptr, nullptr, ids, emb, 1024, 2048);
    // logits = attnAll @ Wfc + bfc
    gemm_big<1><<<dim3(250, 16), 256>>>(nullptr, Wfc, bfc, out, ids, emb, 32000, 1024);
}

// round 8
// speedup vs baseline: 1.7381x; 1.5513x over previous
#include <cuda_runtime.h>
#include <cuda_bf16.h>
#include <stdint.h>
#include <math.h>

#define BB 32
#define TT 63
#define TIN_ 64
#define DD 1024
#define EE 256
#define VV 32000
#define NZ 4096
#define MROWS 2016
#define MPAD 2048
#define NSPLIT 8

// ---- persistent scratch (static __device__, no allocation) ----
__device__ __align__(128) float g_h[BB*DD];
__device__ __align__(128) float g_c[BB*DD];
__device__ __align__(128) float g_zero[BB*DD];
__device__ __align__(128) float g_keys[BB*TIN_*DD];
__device__ __align__(128) float g_attnAll[MPAD*DD];
__device__ __align__(128) float g_zpart[NSPLIT*BB*NZ];
__device__ __align__(128) float g_embW[MPAD*NZ];
__device__ __align__(128) float g_Wz[2*DD*NZ];
__device__ __align__(128) float g_hHist[MPAD*DD];
__device__ __align__(128) float g_ctxHist[MPAD*DD];
// bf16-split operands for the tensor-core logits GEMM
__device__ __align__(128) __nv_bfloat16 g_Ahi[MPAD*DD];
__device__ __align__(128) __nv_bfloat16 g_Alo[MPAD*DD];
__device__ __align__(128) __nv_bfloat16 g_WhiT[(size_t)VV*DD];   // [n][k] K-major
__device__ __align__(128) __nv_bfloat16 g_WloT[(size_t)VV*DD];

// Blackwell packed fp32x2 FMA (SASS FFMA2)
__device__ __forceinline__ unsigned long long fma2(unsigned long long a,
                                                   unsigned long long b,
                                                   unsigned long long c) {
    unsigned long long d;
    asm("fma.rn.f32x2 %0, %1, %2, %3;" : "=l"(d) : "l"(a), "l"(b), "l"(c));
    return d;
}
__device__ __forceinline__ float sigm(float x) { return 1.f / (1.f + expf(-x)); }

__global__ void init_kernel(const float* __restrict__ h0, const float* __restrict__ c0) {
    int i = blockIdx.x * blockDim.x + threadIdx.x;
    g_h[i] = h0[i];
    g_c[i] = c0[i];
    g_zero[i] = 0.f;
}

// ============================================================================
// gemm_big (FFMA2): MODE 0 keys, MODE 2 Wz, MODE 3 embW, MODE 4 attnAll
// ============================================================================
template<int MODE>
__global__ __launch_bounds__(256, 2)
void gemm_big(const float* __restrict__ Aext, const float* __restrict__ Bw,
              const float* __restrict__ aux, float* __restrict__ Cext,
              const int* __restrict__ ids, const float* __restrict__ emb,
              int N, int K)
{
    __shared__ float2 As[2][16][128];
    __shared__ float  Bs[2][16][128];

    const int tx = threadIdx.x & 15, ty = threadIdx.x >> 4;
    const int bm = blockIdx.y * 128, bn = blockIdx.x * 128;
    const int am = threadIdx.x >> 1, ak = (threadIdx.x & 1) * 8;
    const int bk = threadIdx.x >> 4, bq = (threadIdx.x & 15) * 8;
    const int m  = bm + am;

    const float* Arow = nullptr;
    if (MODE == 0 || MODE == 2) Arow = Aext + (size_t)m * K + ak;
    else if (MODE == 3) {
        int mm = (m < MROWS) ? m : (MROWS - 1);
        Arow = emb + (size_t)ids[(mm & 31) * TT + (mm >> 5)] * EE + ak;
    }
    const float* Bcol = Bw + bn + bq;

    unsigned long long acc[8][4];
#pragma unroll
    for (int i = 0; i < 8; i++)
#pragma unroll
        for (int j = 0; j < 4; j++) acc[i][j] = 0ull;

    float4 a0, a1, b0, b1;

#define GB_LOAD(K0)                                                            \
    {                                                                          \
        if (MODE == 4) {                                                       \
            if (m >= MROWS) { a0 = make_float4(0,0,0,0); a1 = a0; }            \
            else {                                                             \
                int kg = (K0) + ak;                                            \
                const float* p = (kg < DD)                                     \
                    ? (g_hHist   + (size_t)m * DD + kg)                        \
                    : (g_ctxHist + (size_t)m * DD + (kg - DD));                \
                a0 = *(const float4*)p; a1 = *(const float4*)(p + 4);          \
            }                                                                  \
        } else {                                                               \
            a0 = *(const float4*)(Arow + (K0));                                \
            a1 = *(const float4*)(Arow + (K0) + 4);                            \
        }                                                                      \
        b0 = *(const float4*)(Bcol + (size_t)((K0) + bk) * N);                 \
        b1 = *(const float4*)(Bcol + (size_t)((K0) + bk) * N + 4);             \
    }

#define GB_STORE(BUF)                                                          \
    {                                                                          \
        As[BUF][ak+0][am] = make_float2(a0.x, a0.x);                           \
        As[BUF][ak+1][am] = make_float2(a0.y, a0.y);                           \
        As[BUF][ak+2][am] = make_float2(a0.z, a0.z);                           \
        As[BUF][ak+3][am] = make_float2(a0.w, a0.w);                           \
        As[BUF][ak+4][am] = make_float2(a1.x, a1.x);                           \
        As[BUF][ak+5][am] = make_float2(a1.y, a1.y);                           \
        As[BUF][ak+6][am] = make_float2(a1.z, a1.z);                           \
        As[BUF][ak+7][am] = make_float2(a1.w, a1.w);                           \
        *(float4*)&Bs[BUF][bk][bq]     = b0;                                   \
        *(float4*)&Bs[BUF][bk][bq + 4] = b1;                                   \
    }

    const int NT = K / 16;
    GB_LOAD(0)
    GB_STORE(0)
    __syncthreads();

    for (int tile = 0; tile < NT; tile++) {
        int cur = tile & 1;
        if (tile + 1 < NT) GB_LOAD((tile + 1) * 16)
#pragma unroll
        for (int kk = 0; kk < 16; kk++) {
            unsigned long long av[8], bv[4];
#pragma unroll
            for (int i = 0; i < 8; i++)
                av[i] = *reinterpret_cast<const unsigned long long*>(&As[cur][kk][ty*8 + i]);
#pragma unroll
            for (int j = 0; j < 4; j++)
                bv[j] = *reinterpret_cast<const unsigned long long*>(&Bs[cur][kk][tx*2 + 32*j]);
#pragma unroll
            for (int i = 0; i < 8; i++)
#pragma unroll
                for (int j = 0; j < 4; j++)
                    acc[i][j] = fma2(av[i], bv[j], acc[i][j]);
        }
        if (tile + 1 < NT) { GB_STORE(cur ^ 1) __syncthreads(); }
    }
#undef GB_LOAD
#undef GB_STORE

#pragma unroll
    for (int i = 0; i < 8; i++) {
        int mo = bm + ty*8 + i;
#pragma unroll
        for (int j = 0; j < 4; j++) {
            int n = bn + tx*2 + 32*j;
            float2 v = *reinterpret_cast<float2*>(&acc[i][j]);
            if (MODE == 0) {
                *(float2*)&g_keys[(size_t)mo * DD + n] = v;
            } else if (MODE == 2) {
                if (mo < DD) { v.x += aux[(size_t)mo*NZ + n]; v.y += aux[(size_t)mo*NZ + n + 1]; }
                *(float2*)&g_Wz[(size_t)mo * NZ + n] = v;
            } else if (MODE == 3) {
                *(float2*)&g_embW[(size_t)mo * NZ + n] = v;
            } else if (MODE == 4) {
                *(float2*)&g_attnAll[(size_t)mo * DD + n] = v;
            }
        }
    }
}

// ============================================================================
// zstep_gemm: z partials = [h ; ctx_prev] @ [Btop ; Wcomb_bot]
// ============================================================================
__global__ __launch_bounds__(256)
void zstep_gemm(const float* __restrict__ Wh, int t)
{
    __shared__ float2 As[2][16][33];
    __shared__ float  Bs[2][16][128];

    const float* Btop    = (t == 0) ? Wh : g_Wz;
    const float* Bbot    = g_Wz + (size_t)DD * NZ;
    const float* ctxprev = (t == 0) ? g_zero : (g_ctxHist + (size_t)(t - 1) * BB * DD);

    const int s  = blockIdx.z;
    const int bn = blockIdx.x * 128;
    const int kb = s * 256;
    const int nx = threadIdx.x & 31, my = threadIdx.x >> 5;
    const int am = threadIdx.x >> 3, ak = (threadIdx.x & 7) * 2;
    const int bk = threadIdx.x >> 4, bq = (threadIdx.x & 15) * 8;

    unsigned long long acc[4][2];
#pragma unroll
    for (int i = 0; i < 4; i++)
#pragma unroll
        for (int j = 0; j < 2; j++) acc[i][j] = 0ull;

    float2 a; float4 b0, b1;

#define ZS_LOAD(K0)                                                            \
    {                                                                          \
        int kg = kb + (K0) + ak;                                               \
        const float* ap = (kg < DD) ? (g_h + am*DD + kg)                       \
                                    : (ctxprev + am*DD + (kg - DD));           \
        a = *(const float2*)ap;                                                \
        int kr = kb + (K0) + bk;                                               \
        const float* brow = (kr < DD) ? (Btop + (size_t)kr * NZ)               \
                                      : (Bbot + (size_t)(kr - DD) * NZ);       \
        b0 = *(const float4*)(brow + bn + bq);                                 \
        b1 = *(const float4*)(brow + bn + bq + 4);                             \
    }

#define ZS_STORE(BUF)                                                          \
    {                                                                          \
        As[BUF][ak+0][am] = make_float2(a.x, a.x);                             \
        As[BUF][ak+1][am] = make_float2(a.y, a.y);                             \
        *(float4*)&Bs[BUF][bk][bq]     = b0;                                   \
        *(float4*)&Bs[BUF][bk][bq + 4] = b1;                                   \
    }

    const int NT = 16;
    ZS_LOAD(0)
    ZS_STORE(0)
    __syncthreads();

    for (int tile = 0; tile < NT; tile++) {
        int cur = tile & 1;
        if (tile + 1 < NT) ZS_LOAD((tile + 1) * 16)
#pragma unroll
        for (int kk = 0; kk < 16; kk++) {
            unsigned long long av[4], bv[2];
#pragma unroll
            for (int i = 0; i < 4; i++)
                av[i] = *reinterpret_cast<const unsigned long long*>(&As[cur][kk][my*4 + i]);
#pragma unroll
            for (int j = 0; j < 2; j++)
                bv[j] = *reinterpret_cast<const unsigned long long*>(&Bs[cur][kk][nx*2 + 64*j]);
#pragma unroll
            for (int i = 0; i < 4; i++)
#pragma unroll
                for (int j = 0; j < 2; j++)
                    acc[i][j] = fma2(av[i], bv[j], acc[i][j]);
        }
        if (tile + 1 < NT) { ZS_STORE(cur ^ 1) __syncthreads(); }
    }
#undef ZS_LOAD
#undef ZS_STORE

#pragma unroll
    for (int i = 0; i < 4; i++) {
        int b = my*4 + i;
#pragma unroll
        for (int j = 0; j < 2; j++) {
            int n = bn + nx*2 + 64*j;
            *(float2*)&g_zpart[(size_t)(s*BB + b) * NZ + n] =
                *reinterpret_cast<float2*>(&acc[i][j]);
        }
    }
}

// ============================================================================
// step_fused: z-combine + LSTM gates + scores + softmax + context
// ============================================================================
#define ACC2(v, p) { float2 _t = *(const float2*)(p); v.x += _t.x; v.y += _t.y; }

__global__ __launch_bounds__(512)
void step_fused(const float* __restrict__ b4, const float* __restrict__ scale,
                const float* __restrict__ memory, int t)
{
    __shared__ __align__(16) float h_s[DD];
    __shared__ float sc[TIN_];
    __shared__ float al_s[TIN_];
    const int b = blockIdx.x, tid = threadIdx.x;
    const int j0 = tid * 2;

    float2 zi = *(const float2*)(b4 + j0);
    float2 zf = *(const float2*)(b4 + DD + j0);
    float2 zg = *(const float2*)(b4 + 2*DD + j0);
    float2 zo = *(const float2*)(b4 + 3*DD + j0);
    const float* ew = g_embW + ((size_t)t*BB + b) * NZ;
    ACC2(zi, ew + j0); ACC2(zf, ew + DD + j0); ACC2(zg, ew + 2*DD + j0); ACC2(zo, ew + 3*DD + j0);
#pragma unroll
    for (int s = 0; s < NSPLIT; s++) {
        const float* zp = g_zpart + (size_t)(s*BB + b) * NZ;
        ACC2(zi, zp + j0); ACC2(zf, zp + DD + j0);
        ACC2(zg, zp + 2*DD + j0); ACC2(zo, zp + 3*DD + j0);
    }
    float2 c = *(const float2*)(g_c + b*DD + j0);
    float2 cn, hn;
    cn.x = sigm(zf.x) * c.x + sigm(zi.x) * tanhf(zg.x);
    cn.y = sigm(zf.y) * c.y + sigm(zi.y) * tanhf(zg.y);
    hn.x = sigm(zo.x) * tanhf(cn.x);
    hn.y = sigm(zo.y) * tanhf(cn.y);
    *(float2*)(g_c + b*DD + j0) = cn;
    *(float2*)(g_h + b*DD + j0) = hn;
    *(float2*)(g_hHist + ((size_t)t*BB + b)*DD + j0) = hn;
    *(float2*)(h_s + j0) = hn;
    __syncthreads();

    const int w = tid >> 5, lane = tid & 31;
    const float4* hv4 = (const float4*)h_s;
    float4 hreg[8];
#pragma unroll
    for (int it = 0; it < 8; it++) hreg[it] = hv4[it*32 + lane];
    const float sc0 = scale[0];
    float pa[4] = {0.f, 0.f, 0.f, 0.f};
#pragma unroll
    for (int p = 0; p < 4; p++) {
        const float4* kr = (const float4*)(g_keys + ((size_t)b*TIN_ + w*4 + p) * DD);
#pragma unroll
        for (int it = 0; it < 8; it++) {
            float4 kv = kr[it*32 + lane];
            pa[p] += kv.x*hreg[it].x + kv.y*hreg[it].y + kv.z*hreg[it].z + kv.w*hreg[it].w;
        }
    }
#pragma unroll
    for (int p = 0; p < 4; p++) {
        float v = pa[p];
#pragma unroll
        for (int off = 16; off > 0; off >>= 1)
            v += __shfl_xor_sync(0xffffffffu, v, off);
        if (lane == 0) sc[w*4 + p] = v * sc0;
    }
    __syncthreads();

    if (tid < 32) {
        float a = sc[tid], c2 = sc[tid + 32];
        float mx = fmaxf(a, c2);
#pragma unroll
        for (int off = 16; off > 0; off >>= 1)
            mx = fmaxf(mx, __shfl_xor_sync(0xffffffffu, mx, off));
        float ea = expf(a - mx), eb = expf(c2 - mx);
        float ssum = ea + eb;
#pragma unroll
        for (int off = 16; off > 0; off >>= 1)
            ssum += __shfl_xor_sync(0xffffffffu, ssum, off);
        float inv = 1.f / ssum;
        al_s[tid] = ea * inv;
        al_s[tid + 32] = eb * inv;
    }
    __syncthreads();

    const float* mb = memory + (size_t)b * TIN_ * DD;
    float* ch = g_ctxHist + ((size_t)t*BB + b) * DD;
#pragma unroll
    for (int q = 0; q < 2; q++) {
        int d = tid + q * 512;
        float acc = 0.f;
#pragma unroll 8
        for (int tt2 = 0; tt2 < TIN_; tt2++)
            acc += al_s[tt2] * mb[(size_t)tt2 * DD + d];
        ch[d] = acc;
    }
}

// ============================================================================
// bf16-split conversion kernels
// ============================================================================
__global__ void conv_a() {
    int i = blockIdx.x * 256 + threadIdx.x;       // grid 8192
    float v = g_attnAll[i];
    __nv_bfloat16 h = __float2bfloat16(v);
    g_Ahi[i] = h;
    g_Alo[i] = __float2bfloat16(v - __bfloat162float(h));
}

// transpose + split: Wfc [1024][32000] -> WhiT/WloT [32000][1024]
__global__ void conv_w(const float* __restrict__ Wfc) {
    __shared__ float tile[32][33];
    int n0 = blockIdx.x * 32, k0 = blockIdx.y * 32;
    int tx = threadIdx.x, ty = threadIdx.y;       // (32, 8)
#pragma unroll
    for (int i = 0; i < 4; i++)
        tile[ty + i*8][tx] = Wfc[(size_t)(k0 + ty + i*8) * VV + n0 + tx];
    __syncthreads();
#pragma unroll
    for (int i = 0; i < 4; i++) {
        float v = tile[tx][ty + i*8];
        __nv_bfloat16 h = __float2bfloat16(v);
        size_t o = (size_t)(n0 + ty + i*8) * DD + k0 + tx;
        g_WhiT[o] = h;
        g_WloT[o] = __float2bfloat16(v - __bfloat162float(h));
    }
}

// ============================================================================
// logits_mma: bf16-split GEMM via mma.sync (sm_80-era PTX, works on sm_103 plain)
// C[2048,32000] = Ahi@Bhi + Ahi@Blo + Alo@Bhi  (+bias, permuted store)
// CTA tile 128x128, BK=64, 256 thr, 8 warps (2m x 4n), warp tile 64x32.
// ============================================================================
#define LMATB 16384                 // bytes per 128x64 bf16 matrix
#define LSTAGE (4*LMATB)            // 64KB: Ahi,Alo,Bhi,Blo
#define LSMEM (2*LSTAGE)            // 128KB double-buffered

__device__ __forceinline__ uint32_t sw128(uint32_t x) { return x ^ ((x >> 3) & 0x70); }
__device__ __forceinline__ uint32_t smem_u32(const void* p) {
    uint32_t a;
    asm("{ .reg .u64 t; cvta.to.shared.u64 t, %1; cvt.u32.u64 %0, t; }" : "=r"(a) : "l"(p));
    return a;
}
__device__ __forceinline__ void cpa16(uint32_t dst, const __nv_bfloat16* src) {
    asm volatile("cp.async.cg.shared.global [%0], [%1], 16;"
                 :: "r"(dst), "l"(__cvta_generic_to_global(src)) : "memory");
}
__device__ __forceinline__ void ldsm4(uint32_t& r0, uint32_t& r1, uint32_t& r2, uint32_t& r3,
                                      uint32_t a) {
    asm volatile("ldmatrix.sync.aligned.m8n8.x4.shared.b16 {%0,%1,%2,%3}, [%4];"
                 : "=r"(r0), "=r"(r1), "=r"(r2), "=r"(r3) : "r"(a));
}
__device__ __forceinline__ void mma16816(float* c, const uint32_t* a, const uint32_t* b) {
    asm volatile("mma.sync.aligned.m16n8k16.row.col.f32.bf16.bf16.f32 "
                 "{%0,%1,%2,%3}, {%4,%5,%6,%7}, {%8,%9}, {%0,%1,%2,%3};"
                 : "+f"(c[0]), "+f"(c[1]), "+f"(c[2]), "+f"(c[3])
                 : "r"(a[0]), "r"(a[1]), "r"(a[2]), "r"(a[3]), "r"(b[0]), "r"(b[1]));
}

__device__ __forceinline__ void lm_stage(uint32_t sb, int m0, int n0, int k0, int tid) {
#pragma unroll
    for (int i = 0; i < 16; i++) {
        int idx = tid + i * 256;            // 0..4095
        int mat = idx >> 10;                // 0 Ahi, 1 Alo, 2 Bhi, 3 Blo
        int r   = (idx >> 3) & 127;
        int s   = idx & 7;
        const __nv_bfloat16* base =
            (mat == 0) ? g_Ahi : (mat == 1) ? g_Alo : (mat == 2) ? g_WhiT : g_WloT;
        int rowg = ((mat < 2) ? m0 : n0) + r;
        cpa16(sb + mat * LMATB + sw128(r * 128 + s * 16),
              base + (size_t)rowg * DD + k0 + s * 8);
    }
    asm volatile("cp.async.commit_group;" ::: "memory");
}

__global__ __launch_bounds__(256)
void logits_mma(const float* __restrict__ bfc, float* __restrict__ out)
{
    extern __shared__ char dsm[];
    const uint32_t sb0 = smem_u32(dsm);
    const int tid = threadIdx.x, wid = tid >> 5, lane = tid & 31;
    const int m0 = blockIdx.x * 128, n0 = blockIdx.y * 128;
    const int wm = wid >> 2, wn = wid & 3;     // warp 64x32 tile

    float acc[4][4][4];
#pragma unroll
    for (int i = 0; i < 4; i++)
#pragma unroll
        for (int j = 0; j < 4; j++)
#pragma unroll
            for (int k = 0; k < 4; k++) acc[i][j][k] = 0.f;

    lm_stage(sb0, m0, n0, 0, tid);

    const int NCH = DD / 64;                   // 16
    for (int ch = 0; ch < NCH; ch++) {
        const uint32_t cb = sb0 + (ch & 1) * LSTAGE;
        asm volatile("cp.async.wait_group 0;" ::: "memory");
        __syncthreads();
        if (ch + 1 < NCH)
            lm_stage(sb0 + ((ch + 1) & 1) * LSTAGE, m0, n0, (ch + 1) * 64, tid);

        const uint32_t Ah = cb, Al = cb + LMATB, Bh = cb + 2*LMATB, Bl = cb + 3*LMATB;
#pragma unroll
        for (int ks = 0; ks < 4; ks++) {
            const int kb = ks * 32;            // byte col of this k16
            uint32_t ahi[4][4], alo[4][4];
#pragma unroll
            for (int mf = 0; mf < 4; mf++) {
                uint32_t off = sw128((wm*64 + mf*16 + (lane & 15)) * 128
                                     + kb + (lane >> 4) * 16);
                ldsm4(ahi[mf][0], ahi[mf][1], ahi[mf][2], ahi[mf][3], Ah + off);
                ldsm4(alo[mf][0], alo[mf][1], alo[mf][2], alo[mf][3], Al + off);
            }
            uint32_t bhi[4][2], blo[4][2];
#pragma unroll
            for (int p = 0; p < 2; p++) {
                int q = lane >> 3;
                uint32_t off = sw128((wn*32 + p*16 + ((q >> 1) & 1)*8 + (lane & 7)) * 128
                                     + kb + (q & 1) * 16);
                ldsm4(bhi[2*p][0], bhi[2*p][1], bhi[2*p+1][0], bhi[2*p+1][1], Bh + off);
                ldsm4(blo[2*p][0], blo[2*p][1], blo[2*p+1][0], blo[2*p+1][1], Bl + off);
            }
#pragma unroll
            for (int mf = 0; mf < 4; mf++)
#pragma unroll
                for (int nf = 0; nf < 4; nf++) {
                    mma16816(acc[mf][nf], ahi[mf], bhi[nf]);
                    mma16816(acc[mf][nf], ahi[mf], blo[nf]);
                    mma16816(acc[mf][nf], alo[mf], bhi[nf]);
                }
        }
        __syncthreads();
    }

    // epilogue: bias + permuted store  (C frag: c0,c1 @ (row=lane/4, col=2*(lane%4)),
    //                                   c2,c3 @ row+8)
    float2 bias[4];
#pragma unroll
    for (int nf = 0; nf < 4; nf++)
        bias[nf] = *(const float2*)&bfc[n0 + wn*32 + nf*8 + (lane & 3)*2];

#pragma unroll
    for (int mf = 0; mf < 4; mf++) {
#pragma unroll
        for (int half = 0; half < 2; half++) {
            int m = m0 + wm*64 + mf*16 + (lane >> 2) + half*8;
            if (m < MROWS) {
                float* orow = out + ((size_t)(m & 31) * TT + (m >> 5)) * VV;
#pragma unroll
                for (int nf = 0; nf < 4; nf++) {
                    int n = n0 + wn*32 + nf*8 + (lane & 3)*2;
                    float2 v;
                    v.x = acc[mf][nf][half*2 + 0] + bias[nf].x;
                    v.y = acc[mf][nf][half*2 + 1] + bias[nf].y;
                    *(float2*)&orow[n] = v;
                }
            }
        }
    }
}

extern "C" void kernel_launch(void* const* d_in, const int* in_sizes, int n_in,
                              void* d_out, int out_size) {
    const int*   ids    = (const int*)  d_in[0];
    const float* h0     = (const float*)d_in[1];
    const float* c0     = (const float*)d_in[2];
    const float* memory = (const float*)d_in[3];
    const float* emb    = (const float*)d_in[4];
    const float* Wx     = (const float*)d_in[5];
    const float* Wh     = (const float*)d_in[6];
    const float* b4     = (const float*)d_in[7];
    const float* Wm     = (const float*)d_in[8];
    const float* scale  = (const float*)d_in[9];
    const float* Wa     = (const float*)d_in[10];
    const float* Wfc    = (const float*)d_in[11];
    const float* bfc    = (const float*)d_in[12];
    float* out = (float*)d_out;

    cudaFuncSetAttribute(logits_mma, cudaFuncAttributeMaxDynamicSharedMemorySize, LSMEM);

    init_kernel<<<128, 256>>>(h0, c0);

    // one-time weight transform for tensor-core logits GEMM
    conv_w<<<dim3(VV/32, DD/32), dim3(32, 8)>>>(Wfc);

    // keys = memory @ Wm
    gemm_big<0><<<dim3(8, 16), 256>>>(memory, Wm, nullptr, nullptr, ids, emb, 1024, 1024);
    // Wz = [Wh + Wa_h@Wx_attn ; Wa_ctx@Wx_attn]
    gemm_big<2><<<dim3(32, 16), 256>>>(Wa, Wx + 256*4096, Wh, nullptr, ids, emb, 4096, 1024);
    // embW = emb[ids] @ Wx_emb
    gemm_big<3><<<dim3(32, 16), 256>>>(nullptr, Wx, nullptr, nullptr, ids, emb, 4096, 256);

    for (int t = 0; t < TT; t++) {
        zstep_gemm<<<dim3(32, 1, NSPLIT), 256>>>(Wh, t);
        step_fused<<<BB, 512>>>(b4, scale, memory, t);
    }

    // attnAll = [hHist, ctxHist] @ Wa  (pad rows -> 0)
    gemm_big<4><<<dim3(8, 16), 256>>>(nullptr, Wa, nullptr, nullptr, ids, emb, 1024, 2048);
    conv_a<<<8192, 256>>>();

    // logits = attnAll @ Wfc + bfc via mma.sync bf16 hi/lo split, fp32 acc
    logits_mma<<<dim3(16, 250), 256, LSMEM>>>(bfc, out);
}

// round 11
// speedup vs baseline: 2.0071x; 1.1547x over previous
#include <cuda_runtime.h>
#include <cuda_bf16.h>
#include <stdint.h>
#include <math.h>

#define BB 32
#define TT 63
#define TIN_ 64
#define DD 1024
#define EE 256
#define VV 32000
#define NZ 4096
#define MROWS 2016
#define MPAD 2048
#define NSPLIT 8

// ---- persistent scratch (static __device__, no allocation) ----
__device__ __align__(128) float g_h[BB*DD];
__device__ __align__(128) float g_c[BB*DD];
__device__ __align__(128) float g_zero[BB*DD];
__device__ __align__(128) float g_keys[BB*TIN_*DD];
__device__ __align__(128) float g_zpart[NSPLIT*BB*NZ];
__device__ __align__(128) float g_embW[MPAD*NZ];
__device__ __align__(128) float g_Wz[2*DD*NZ];
__device__ __align__(128) float g_hHist[MPAD*DD];
__device__ __align__(128) float g_ctxHist[MPAD*DD];
// bf16-split operands
__device__ __align__(128) __nv_bfloat16 g_Ahi[MPAD*DD];      // attnAll split (A of logits)
__device__ __align__(128) __nv_bfloat16 g_Alo[MPAD*DD];
__device__ __align__(128) __nv_bfloat16 g_WhiT[(size_t)VV*DD];
__device__ __align__(128) __nv_bfloat16 g_WloT[(size_t)VV*DD];
__device__ __align__(128) __nv_bfloat16 g_WxaT_hi[(size_t)NZ*DD];
__device__ __align__(128) __nv_bfloat16 g_WxaT_lo[(size_t)NZ*DD];
__device__ __align__(128) __nv_bfloat16 g_WxeT_hi[(size_t)NZ*EE];
__device__ __align__(128) __nv_bfloat16 g_WxeT_lo[(size_t)NZ*EE];
__device__ __align__(128) __nv_bfloat16 g_WmT_hi[(size_t)DD*DD];
__device__ __align__(128) __nv_bfloat16 g_WmT_lo[(size_t)DD*DD];
__device__ __align__(128) __nv_bfloat16 g_WaT_hi[(size_t)DD*2*DD];
__device__ __align__(128) __nv_bfloat16 g_WaT_lo[(size_t)DD*2*DD];
__device__ __align__(128) __nv_bfloat16 g_Wa_hi[(size_t)2*DD*DD];
__device__ __align__(128) __nv_bfloat16 g_Wa_lo[(size_t)2*DD*DD];
__device__ __align__(128) __nv_bfloat16 g_mem_hi[MPAD*DD];
__device__ __align__(128) __nv_bfloat16 g_mem_lo[MPAD*DD];
__device__ __align__(128) __nv_bfloat16 g_emb_hi[MPAD*EE];
__device__ __align__(128) __nv_bfloat16 g_emb_lo[MPAD*EE];
__device__ __align__(128) __nv_bfloat16 g_AX_hi[MPAD*2*DD];
__device__ __align__(128) __nv_bfloat16 g_AX_lo[MPAD*2*DD];

// Blackwell packed fp32x2 FMA (SASS FFMA2)
__device__ __forceinline__ unsigned long long fma2(unsigned long long a,
                                                   unsigned long long b,
                                                   unsigned long long c) {
    unsigned long long d;
    asm("fma.rn.f32x2 %0, %1, %2, %3;" : "=l"(d) : "l"(a), "l"(b), "l"(c));
    return d;
}
__device__ __forceinline__ float sigm(float x) { return 1.f / (1.f + expf(-x)); }

__global__ void init_kernel(const float* __restrict__ h0, const float* __restrict__ c0) {
    int i = blockIdx.x * blockDim.x + threadIdx.x;
    g_h[i] = h0[i];
    g_c[i] = c0[i];
    g_zero[i] = 0.f;
}

// ============================================================================
// tsplit<MODE>: transpose + hi/lo split, src fp32 [K][N] -> (device-global) [N][K]
// MODE 0: Wfc->WhiT/WloT  1: Wxa->WxaT  2: Wxe->WxeT  3: Wm->WmT  4: Wa->WaT
// ============================================================================
template<int MODE>
__global__ void tsplit(const float* __restrict__ src, int K, int N)
{
    __nv_bfloat16* dhi; __nv_bfloat16* dlo;
    if (MODE == 0)      { dhi = g_WhiT;    dlo = g_WloT;    }
    else if (MODE == 1) { dhi = g_WxaT_hi; dlo = g_WxaT_lo; }
    else if (MODE == 2) { dhi = g_WxeT_hi; dlo = g_WxeT_lo; }
    else if (MODE == 3) { dhi = g_WmT_hi;  dlo = g_WmT_lo;  }
    else                { dhi = g_WaT_hi;  dlo = g_WaT_lo;  }

    __shared__ float tile[32][33];
    int n0 = blockIdx.x * 32, k0 = blockIdx.y * 32;
    int tx = threadIdx.x, ty = threadIdx.y;
#pragma unroll
    for (int i = 0; i < 4; i++)
        tile[ty + i*8][tx] = src[(size_t)(k0 + ty + i*8) * N + n0 + tx];
    __syncthreads();
#pragma unroll
    for (int i = 0; i < 4; i++) {
        float v = tile[tx][ty + i*8];
        __nv_bfloat16 h = __float2bfloat16(v);
        size_t o = (size_t)(n0 + ty + i*8) * K + k0 + tx;
        dhi[o] = h;
        dlo[o] = __float2bfloat16(v - __bfloat162float(h));
    }
}

// rsplit<MODE>: element-wise hi/lo split. MODE 0: Wa -> g_Wa. MODE 1: memory -> g_mem.
template<int MODE>
__global__ void rsplit(const float* __restrict__ src)
{
    __nv_bfloat16* dhi = (MODE == 0) ? g_Wa_hi : g_mem_hi;
    __nv_bfloat16* dlo = (MODE == 0) ? g_Wa_lo : g_mem_lo;
    int i = blockIdx.x * 256 + threadIdx.x;
    float v = src[i];
    __nv_bfloat16 h = __float2bfloat16(v);
    dhi[i] = h;
    dlo[i] = __float2bfloat16(v - __bfloat162float(h));
}

// gathered embedding split: rows (t*32+b) of emb[ids] -> g_emb_hi/lo [2048][256]
__global__ void split_emb(const float* __restrict__ emb, const int* __restrict__ ids) {
    int i = blockIdx.x * 256 + threadIdx.x;
    int m = i >> 8, k = i & 255;
    float v = 0.f;
    if (m < MROWS) v = emb[(size_t)ids[(m & 31) * TT + (m >> 5)] * EE + k];
    __nv_bfloat16 h = __float2bfloat16(v);
    g_emb_hi[i] = h;
    g_emb_lo[i] = __float2bfloat16(v - __bfloat162float(h));
}

// concat [hHist, ctxHist] split -> g_AX_hi/lo [2048][2048] (pad rows zero)
__global__ void split_ax() {
    int i = blockIdx.x * 256 + threadIdx.x;
    int m = i >> 11, k = i & 2047;
    float v = 0.f;
    if (m < MROWS)
        v = (k < DD) ? g_hHist[(size_t)m * DD + k] : g_ctxHist[(size_t)m * DD + (k - DD)];
    __nv_bfloat16 h = __float2bfloat16(v);
    g_AX_hi[i] = h;
    g_AX_lo[i] = __float2bfloat16(v - __bfloat162float(h));
}

// ============================================================================
// zstep_gemm: z partials = [h ; ctx_prev] @ [Btop ; Wcomb_bot]  (fp32 FFMA2)
// ============================================================================
__global__ __launch_bounds__(256)
void zstep_gemm(const float* __restrict__ Wh, int t)
{
    __shared__ float2 As[2][16][33];
    __shared__ float  Bs[2][16][128];

    const float* Btop    = (t == 0) ? Wh : g_Wz;
    const float* Bbot    = g_Wz + (size_t)DD * NZ;
    const float* ctxprev = (t == 0) ? g_zero : (g_ctxHist + (size_t)(t - 1) * BB * DD);

    const int s  = blockIdx.z;
    const int bn = blockIdx.x * 128;
    const int kb = s * 256;
    const int nx = threadIdx.x & 31, my = threadIdx.x >> 5;
    const int am = threadIdx.x >> 3, ak = (threadIdx.x & 7) * 2;
    const int bk = threadIdx.x >> 4, bq = (threadIdx.x & 15) * 8;

    unsigned long long acc[4][2];
#pragma unroll
    for (int i = 0; i < 4; i++)
#pragma unroll
        for (int j = 0; j < 2; j++) acc[i][j] = 0ull;

    float2 a; float4 b0, b1;

#define ZS_LOAD(K0)                                                            \
    {                                                                          \
        int kg = kb + (K0) + ak;                                               \
        const float* ap = (kg < DD) ? (g_h + am*DD + kg)                       \
                                    : (ctxprev + am*DD + (kg - DD));           \
        a = *(const float2*)ap;                                                \
        int kr = kb + (K0) + bk;                                               \
        const float* brow = (kr < DD) ? (Btop + (size_t)kr * NZ)               \
                                      : (Bbot + (size_t)(kr - DD) * NZ);       \
        b0 = *(const float4*)(brow + bn + bq);                                 \
        b1 = *(const float4*)(brow + bn + bq + 4);                             \
    }

#define ZS_STORE(BUF)                                                          \
    {                                                                          \
        As[BUF][ak+0][am] = make_float2(a.x, a.x);                             \
        As[BUF][ak+1][am] = make_float2(a.y, a.y);                             \
        *(float4*)&Bs[BUF][bk][bq]     = b0;                                   \
        *(float4*)&Bs[BUF][bk][bq + 4] = b1;                                   \
    }

    const int NT = 16;
    ZS_LOAD(0)
    ZS_STORE(0)
    __syncthreads();

    for (int tile = 0; tile < NT; tile++) {
        int cur = tile & 1;
        if (tile + 1 < NT) ZS_LOAD((tile + 1) * 16)
#pragma unroll
        for (int kk = 0; kk < 16; kk++) {
            unsigned long long av[4], bv[2];
#pragma unroll
            for (int i = 0; i < 4; i++)
                av[i] = *reinterpret_cast<const unsigned long long*>(&As[cur][kk][my*4 + i]);
#pragma unroll
            for (int j = 0; j < 2; j++)
                bv[j] = *reinterpret_cast<const unsigned long long*>(&Bs[cur][kk][nx*2 + 64*j]);
#pragma unroll
            for (int i = 0; i < 4; i++)
#pragma unroll
                for (int j = 0; j < 2; j++)
                    acc[i][j] = fma2(av[i], bv[j], acc[i][j]);
        }
        if (tile + 1 < NT) { ZS_STORE(cur ^ 1) __syncthreads(); }
    }
#undef ZS_LOAD
#undef ZS_STORE

#pragma unroll
    for (int i = 0; i < 4; i++) {
        int b = my*4 + i;
#pragma unroll
        for (int j = 0; j < 2; j++) {
            int n = bn + nx*2 + 64*j;
            *(float2*)&g_zpart[(size_t)(s*BB + b) * NZ + n] =
                *reinterpret_cast<float2*>(&acc[i][j]);
        }
    }
}

// ============================================================================
// step_fused: z-combine + LSTM gates + scores + softmax + context
// ============================================================================
#define ACC2(v, p) { float2 _t = *(const float2*)(p); v.x += _t.x; v.y += _t.y; }

__global__ __launch_bounds__(512)
void step_fused(const float* __restrict__ b4, const float* __restrict__ scale,
                const float* __restrict__ memory, int t)
{
    __shared__ __align__(16) float h_s[DD];
    __shared__ float sc[TIN_];
    __shared__ float al_s[TIN_];
    const int b = blockIdx.x, tid = threadIdx.x;
    const int j0 = tid * 2;

    float2 zi = *(const float2*)(b4 + j0);
    float2 zf = *(const float2*)(b4 + DD + j0);
    float2 zg = *(const float2*)(b4 + 2*DD + j0);
    float2 zo = *(const float2*)(b4 + 3*DD + j0);
    const float* ew = g_embW + ((size_t)t*BB + b) * NZ;
    ACC2(zi, ew + j0); ACC2(zf, ew + DD + j0); ACC2(zg, ew + 2*DD + j0); ACC2(zo, ew + 3*DD + j0);
#pragma unroll
    for (int s = 0; s < NSPLIT; s++) {
        const float* zp = g_zpart + (size_t)(s*BB + b) * NZ;
        ACC2(zi, zp + j0); ACC2(zf, zp + DD + j0);
        ACC2(zg, zp + 2*DD + j0); ACC2(zo, zp + 3*DD + j0);
    }
    float2 c = *(const float2*)(g_c + b*DD + j0);
    float2 cn, hn;
    cn.x = sigm(zf.x) * c.x + sigm(zi.x) * tanhf(zg.x);
    cn.y = sigm(zf.y) * c.y + sigm(zi.y) * tanhf(zg.y);
    hn.x = sigm(zo.x) * tanhf(cn.x);
    hn.y = sigm(zo.y) * tanhf(cn.y);
    *(float2*)(g_c + b*DD + j0) = cn;
    *(float2*)(g_h + b*DD + j0) = hn;
    *(float2*)(g_hHist + ((size_t)t*BB + b)*DD + j0) = hn;
    *(float2*)(h_s + j0) = hn;
    __syncthreads();

    const int w = tid >> 5, lane = tid & 31;
    const float4* hv4 = (const float4*)h_s;
    float4 hreg[8];
#pragma unroll
    for (int it = 0; it < 8; it++) hreg[it] = hv4[it*32 + lane];
    const float sc0 = scale[0];
    float pa[4] = {0.f, 0.f, 0.f, 0.f};
#pragma unroll
    for (int p = 0; p < 4; p++) {
        const float4* kr = (const float4*)(g_keys + ((size_t)b*TIN_ + w*4 + p) * DD);
#pragma unroll
        for (int it = 0; it < 8; it++) {
            float4 kv = kr[it*32 + lane];
            pa[p] += kv.x*hreg[it].x + kv.y*hreg[it].y + kv.z*hreg[it].z + kv.w*hreg[it].w;
        }
    }
#pragma unroll
    for (int p = 0; p < 4; p++) {
        float v = pa[p];
#pragma unroll
        for (int off = 16; off > 0; off >>= 1)
            v += __shfl_xor_sync(0xffffffffu, v, off);
        if (lane == 0) sc[w*4 + p] = v * sc0;
    }
    __syncthreads();

    if (tid < 32) {
        float a = sc[tid], c2 = sc[tid + 32];
        float mx = fmaxf(a, c2);
#pragma unroll
        for (int off = 16; off > 0; off >>= 1)
            mx = fmaxf(mx, __shfl_xor_sync(0xffffffffu, mx, off));
        float ea = expf(a - mx), eb = expf(c2 - mx);
        float ssum = ea + eb;
#pragma unroll
        for (int off = 16; off > 0; off >>= 1)
            ssum += __shfl_xor_sync(0xffffffffu, ssum, off);
        float inv = 1.f / ssum;
        al_s[tid] = ea * inv;
        al_s[tid + 32] = eb * inv;
    }
    __syncthreads();

    const float* mb = memory + (size_t)b * TIN_ * DD;
    float* ch = g_ctxHist + ((size_t)t*BB + b) * DD;
#pragma unroll
    for (int q = 0; q < 2; q++) {
        int d = tid + q * 512;
        float acc = 0.f;
#pragma unroll 8
        for (int tt2 = 0; tt2 < TIN_; tt2++)
            acc += al_s[tt2] * mb[(size_t)tt2 * DD + d];
        ch[d] = acc;
    }
}

// ============================================================================
// mma_gemm<EPI>: bf16-split GEMM via mma.sync. Operands selected DEVICE-SIDE.
// EPI 0: logits (3-term split, bias+permute -> outp arg)
// EPI 1: Wz  = Wa@WxaT (+Wh aux on rows<DD)  -> g_Wz      (4-term, fp32-exact)
// EPI 2: keys = mem@WmT                      -> g_keys    (4-term)
// EPI 3: embW = emb@WxeT                     -> g_embW    (4-term)
// EPI 4: attnAll = AX@WaT -> g_Ahi/g_Alo split             (4-term)
// ============================================================================
#define LMATB 16384
#define LSTAGE (4*LMATB)
#define LSMEM (2*LSTAGE)

__device__ __forceinline__ uint32_t sw128(uint32_t x) { return x ^ ((x >> 3) & 0x70); }
__device__ __forceinline__ uint32_t smem_u32(const void* p) {
    uint32_t a;
    asm("{ .reg .u64 t; cvta.to.shared.u64 t, %1; cvt.u32.u64 %0, t; }" : "=r"(a) : "l"(p));
    return a;
}
__device__ __forceinline__ void cpa16(uint32_t dst, const __nv_bfloat16* src) {
    asm volatile("cp.async.cg.shared.global [%0], [%1], 16;"
                 :: "r"(dst), "l"(__cvta_generic_to_global(src)) : "memory");
}
__device__ __forceinline__ void ldsm4(uint32_t& r0, uint32_t& r1, uint32_t& r2, uint32_t& r3,
                                      uint32_t a) {
    asm volatile("ldmatrix.sync.aligned.m8n8.x4.shared.b16 {%0,%1,%2,%3}, [%4];"
                 : "=r"(r0), "=r"(r1), "=r"(r2), "=r"(r3) : "r"(a));
}
__device__ __forceinline__ void mma16816(float* c, const uint32_t* a, const uint32_t* b) {
    asm volatile("mma.sync.aligned.m16n8k16.row.col.f32.bf16.bf16.f32 "
                 "{%0,%1,%2,%3}, {%4,%5,%6,%7}, {%8,%9}, {%0,%1,%2,%3};"
                 : "+f"(c[0]), "+f"(c[1]), "+f"(c[2]), "+f"(c[3])
                 : "r"(a[0]), "r"(a[1]), "r"(a[2]), "r"(a[3]), "r"(b[0]), "r"(b[1]));
}

__device__ __forceinline__ void lm_stage(uint32_t sb, const __nv_bfloat16* Ahi,
                                         const __nv_bfloat16* Alo,
                                         const __nv_bfloat16* Bhi,
                                         const __nv_bfloat16* Blo,
                                         int m0, int n0, int k0, int K, int tid) {
#pragma unroll
    for (int i = 0; i < 16; i++) {
        int idx = tid + i * 256;
        int mat = idx >> 10;
        int r   = (idx >> 3) & 127;
        int s   = idx & 7;
        const __nv_bfloat16* base =
            (mat == 0) ? Ahi : (mat == 1) ? Alo : (mat == 2) ? Bhi : Blo;
        int rowg = ((mat < 2) ? m0 : n0) + r;
        cpa16(sb + mat * LMATB + sw128(r * 128 + s * 16),
              base + (size_t)rowg * K + k0 + s * 8);
    }
    asm volatile("cp.async.commit_group;" ::: "memory");
}

template<int EPI>
__global__ __launch_bounds__(256)
void mma_gemm(const float* __restrict__ aux, float* __restrict__ outp, int K, int N)
{
    // device-side operand resolution (host cannot take __device__ addresses)
    const __nv_bfloat16 *Ahi, *Alo, *Bhi, *Blo;
    float* dst = outp;
    if (EPI == 0)      { Ahi = g_Ahi;    Alo = g_Alo;    Bhi = g_WhiT;    Blo = g_WloT;    }
    else if (EPI == 1) { Ahi = g_Wa_hi;  Alo = g_Wa_lo;  Bhi = g_WxaT_hi; Blo = g_WxaT_lo; dst = g_Wz;   }
    else if (EPI == 2) { Ahi = g_mem_hi; Alo = g_mem_lo; Bhi = g_WmT_hi;  Blo = g_WmT_lo;  dst = g_keys; }
    else if (EPI == 3) { Ahi = g_emb_hi; Alo = g_emb_lo; Bhi = g_WxeT_hi; Blo = g_WxeT_lo; dst = g_embW; }
    else               { Ahi = g_AX_hi;  Alo = g_AX_lo;  Bhi = g_WaT_hi;  Blo = g_WaT_lo;  }

    extern __shared__ char dsm[];
    const uint32_t sb0 = smem_u32(dsm);
    const int tid = threadIdx.x, wid = tid >> 5, lane = tid & 31;
    const int m0 = blockIdx.x * 128, n0 = blockIdx.y * 128;
    const int wm = wid >> 2, wn = wid & 3;

    float acc[4][4][4];
#pragma unroll
    for (int i = 0; i < 4; i++)
#pragma unroll
        for (int j = 0; j < 4; j++)
#pragma unroll
            for (int k = 0; k < 4; k++) acc[i][j][k] = 0.f;

    lm_stage(sb0, Ahi, Alo, Bhi, Blo, m0, n0, 0, K, tid);

    const int NCH = K / 64;
    for (int ch = 0; ch < NCH; ch++) {
        const uint32_t cb = sb0 + (ch & 1) * LSTAGE;
        asm volatile("cp.async.wait_group 0;" ::: "memory");
        __syncthreads();
        if (ch + 1 < NCH)
            lm_stage(sb0 + ((ch + 1) & 1) * LSTAGE, Ahi, Alo, Bhi, Blo,
                     m0, n0, (ch + 1) * 64, K, tid);

        const uint32_t Ah = cb, Al = cb + LMATB, Bh = cb + 2*LMATB, Bl = cb + 3*LMATB;
#pragma unroll
        for (int ks = 0; ks < 4; ks++) {
            const int kb = ks * 32;
            uint32_t ahi[4][4], alo[4][4];
#pragma unroll
            for (int mf = 0; mf < 4; mf++) {
                uint32_t off = sw128((wm*64 + mf*16 + (lane & 15)) * 128
                                     + kb + (lane >> 4) * 16);
                ldsm4(ahi[mf][0], ahi[mf][1], ahi[mf][2], ahi[mf][3], Ah + off);
                ldsm4(alo[mf][0], alo[mf][1], alo[mf][2], alo[mf][3], Al + off);
            }
            uint32_t bhi[4][2], blo[4][2];
#pragma unroll
            for (int p = 0; p < 2; p++) {
                int q = lane >> 3;
                uint32_t off = sw128((wn*32 + p*16 + ((q >> 1) & 1)*8 + (lane & 7)) * 128
                                     + kb + (q & 1) * 16);
                ldsm4(bhi[2*p][0], bhi[2*p][1], bhi[2*p+1][0], bhi[2*p+1][1], Bh + off);
                ldsm4(blo[2*p][0], blo[2*p][1], blo[2*p+1][0], blo[2*p+1][1], Bl + off);
            }
#pragma unroll
            for (int mf = 0; mf < 4; mf++)
#pragma unroll
                for (int nf = 0; nf < 4; nf++) {
                    mma16816(acc[mf][nf], ahi[mf], bhi[nf]);
                    mma16816(acc[mf][nf], ahi[mf], blo[nf]);
                    mma16816(acc[mf][nf], alo[mf], bhi[nf]);
                    if (EPI != 0) mma16816(acc[mf][nf], alo[mf], blo[nf]);
                }
        }
        __syncthreads();
    }

    if (EPI == 0) {
        float2 bias[4];
#pragma unroll
        for (int nf = 0; nf < 4; nf++)
            bias[nf] = *(const float2*)&aux[n0 + wn*32 + nf*8 + (lane & 3)*2];
#pragma unroll
        for (int mf = 0; mf < 4; mf++) {
#pragma unroll
            for (int half = 0; half < 2; half++) {
                int m = m0 + wm*64 + mf*16 + (lane >> 2) + half*8;
                if (m < MROWS) {
                    float* orow = dst + ((size_t)(m & 31) * TT + (m >> 5)) * VV;
#pragma unroll
                    for (int nf = 0; nf < 4; nf++) {
                        int n = n0 + wn*32 + nf*8 + (lane & 3)*2;
                        float2 v;
                        v.x = acc[mf][nf][half*2 + 0] + bias[nf].x;
                        v.y = acc[mf][nf][half*2 + 1] + bias[nf].y;
                        *(float2*)&orow[n] = v;
                    }
                }
            }
        }
    } else {
#pragma unroll
        for (int mf = 0; mf < 4; mf++) {
#pragma unroll
            for (int half = 0; half < 2; half++) {
                int m = m0 + wm*64 + mf*16 + (lane >> 2) + half*8;
#pragma unroll
                for (int nf = 0; nf < 4; nf++) {
                    int n = n0 + wn*32 + nf*8 + (lane & 3)*2;
                    float2 v;
                    v.x = acc[mf][nf][half*2 + 0];
                    v.y = acc[mf][nf][half*2 + 1];
                    if (EPI == 1 && m < DD) {
                        v.x += aux[(size_t)m * N + n];
                        v.y += aux[(size_t)m * N + n + 1];
                    }
                    if (EPI == 4) {
                        size_t o = (size_t)m * N + n;
                        __nv_bfloat16 hx = __float2bfloat16(v.x);
                        __nv_bfloat16 hy = __float2bfloat16(v.y);
                        g_Ahi[o]     = hx;
                        g_Ahi[o + 1] = hy;
                        g_Alo[o]     = __float2bfloat16(v.x - __bfloat162float(hx));
                        g_Alo[o + 1] = __float2bfloat16(v.y - __bfloat162float(hy));
                    } else {
                        *(float2*)&dst[(size_t)m * N + n] = v;
                    }
                }
            }
        }
    }
}

extern "C" void kernel_launch(void* const* d_in, const int* in_sizes, int n_in,
                              void* d_out, int out_size) {
    const int*   ids    = (const int*)  d_in[0];
    const float* h0     = (const float*)d_in[1];
    const float* c0     = (const float*)d_in[2];
    const float* memory = (const float*)d_in[3];
    const float* emb    = (const float*)d_in[4];
    const float* Wx     = (const float*)d_in[5];
    const float* Wh     = (const float*)d_in[6];
    const float* b4     = (const float*)d_in[7];
    const float* Wm     = (const float*)d_in[8];
    const float* scale  = (const float*)d_in[9];
    const float* Wa     = (const float*)d_in[10];
    const float* Wfc    = (const float*)d_in[11];
    const float* bfc    = (const float*)d_in[12];
    float* out = (float*)d_out;

    cudaFuncSetAttribute(mma_gemm<0>, cudaFuncAttributeMaxDynamicSharedMemorySize, LSMEM);
    cudaFuncSetAttribute(mma_gemm<1>, cudaFuncAttributeMaxDynamicSharedMemorySize, LSMEM);
    cudaFuncSetAttribute(mma_gemm<2>, cudaFuncAttributeMaxDynamicSharedMemorySize, LSMEM);
    cudaFuncSetAttribute(mma_gemm<3>, cudaFuncAttributeMaxDynamicSharedMemorySize, LSMEM);
    cudaFuncSetAttribute(mma_gemm<4>, cudaFuncAttributeMaxDynamicSharedMemorySize, LSMEM);

    init_kernel<<<128, 256>>>(h0, c0);

    // ---- one-time operand prep (bf16 hi/lo), destinations resolved device-side ----
    tsplit<0><<<dim3(VV/32, DD/32),  dim3(32,8)>>>(Wfc, DD, VV);
    tsplit<1><<<dim3(NZ/32, DD/32),  dim3(32,8)>>>(Wx + (size_t)EE*NZ, DD, NZ);
    tsplit<2><<<dim3(NZ/32, EE/32),  dim3(32,8)>>>(Wx, EE, NZ);
    tsplit<3><<<dim3(DD/32, DD/32),  dim3(32,8)>>>(Wm, DD, DD);
    tsplit<4><<<dim3(DD/32, 2*DD/32),dim3(32,8)>>>(Wa, 2*DD, DD);
    rsplit<0><<<(2*DD*DD)/256, 256>>>(Wa);
    rsplit<1><<<(MPAD*DD)/256, 256>>>(memory);
    split_emb<<<(MPAD*EE)/256, 256>>>(emb, ids);

    // keys = memory @ Wm
    mma_gemm<2><<<dim3(16, 8), 256, LSMEM>>>(nullptr, nullptr, DD, DD);
    // Wz = Wa @ Wx_attn (+Wh top)
    mma_gemm<1><<<dim3(16, 32), 256, LSMEM>>>(Wh, nullptr, DD, NZ);
    // embW = emb[ids] @ Wx_emb
    mma_gemm<3><<<dim3(16, 32), 256, LSMEM>>>(nullptr, nullptr, EE, NZ);

    for (int t = 0; t < TT; t++) {
        zstep_gemm<<<dim3(32, 1, NSPLIT), 256>>>(Wh, t);
        step_fused<<<BB, 512>>>(b4, scale, memory, t);
    }

    // attnAll = [hHist,ctxHist] @ Wa -> bf16 hi/lo directly
    split_ax<<<(MPAD*2*DD)/256, 256>>>();
    mma_gemm<4><<<dim3(16, 8), 256, LSMEM>>>(nullptr, nullptr, 2*DD, DD);
    // logits = attnAll @ Wfc + bfc
    mma_gemm<0><<<dim3(16, 250), 256, LSMEM>>>(bfc, out, DD, VV);
}

// round 16
// speedup vs baseline: 2.7781x; 1.3841x over previous
#include <cuda_runtime.h>
#include <cuda_bf16.h>
#include <stdint.h>
#include <math.h>

#define BB 32
#define TT 63
#define TIN_ 64
#define DD 1024
#define EE 256
#define VV 32000
#define NZ 4096
#define SD 2048
#define MROWS 2016
#define MPAD 2048
#define NSPLIT 8

// ---- persistent scratch (static __device__, no allocation) ----
__device__ __align__(128) float g_c[BB*DD];
__device__ __align__(128) float g_keys[BB*TIN_*DD];
__device__ __align__(128) float g_zpart[NSPLIT*BB*NZ];
__device__ __align__(128) float g_embW[MPAD*NZ];
__device__ __align__(128) float g_hHist[MPAD*DD];
__device__ __align__(128) float g_ctxHist[MPAD*DD];
// bf16-split operands
__device__ __align__(128) __nv_bfloat16 g_S_hi[BB*SD];           // state [h|ctx] split
__device__ __align__(128) __nv_bfloat16 g_S_lo[BB*SD];
__device__ __align__(128) __nv_bfloat16 g_WzT_hi[(size_t)NZ*SD]; // combined z weight^T
__device__ __align__(128) __nv_bfloat16 g_WzT_lo[(size_t)NZ*SD];
__device__ __align__(128) __nv_bfloat16 g_WzT0_hi[(size_t)NZ*SD]; // [Wh^T ; 0] (t=0)
__device__ __align__(128) __nv_bfloat16 g_WzT0_lo[(size_t)NZ*SD];
__device__ __align__(128) __nv_bfloat16 g_Ahi[MPAD*DD];          // attnAll split
__device__ __align__(128) __nv_bfloat16 g_Alo[MPAD*DD];
__device__ __align__(128) __nv_bfloat16 g_WhiT[(size_t)VV*DD];
__device__ __align__(128) __nv_bfloat16 g_WloT[(size_t)VV*DD];
__device__ __align__(128) __nv_bfloat16 g_WxaT_hi[(size_t)NZ*DD];
__device__ __align__(128) __nv_bfloat16 g_WxaT_lo[(size_t)NZ*DD];
__device__ __align__(128) __nv_bfloat16 g_WxeT_hi[(size_t)NZ*EE];
__device__ __align__(128) __nv_bfloat16 g_WxeT_lo[(size_t)NZ*EE];
__device__ __align__(128) __nv_bfloat16 g_WmT_hi[(size_t)DD*DD];
__device__ __align__(128) __nv_bfloat16 g_WmT_lo[(size_t)DD*DD];
__device__ __align__(128) __nv_bfloat16 g_WaT_hi[(size_t)DD*2*DD];
__device__ __align__(128) __nv_bfloat16 g_WaT_lo[(size_t)DD*2*DD];
__device__ __align__(128) __nv_bfloat16 g_Wa_hi[(size_t)2*DD*DD];
__device__ __align__(128) __nv_bfloat16 g_Wa_lo[(size_t)2*DD*DD];
__device__ __align__(128) __nv_bfloat16 g_mem_hi[MPAD*DD];
__device__ __align__(128) __nv_bfloat16 g_mem_lo[MPAD*DD];
__device__ __align__(128) __nv_bfloat16 g_emb_hi[MPAD*EE];
__device__ __align__(128) __nv_bfloat16 g_emb_lo[MPAD*EE];
__device__ __align__(128) __nv_bfloat16 g_AX_hi[MPAD*2*DD];
__device__ __align__(128) __nv_bfloat16 g_AX_lo[MPAD*2*DD];

__device__ __forceinline__ float sigm(float x) { return 1.f / (1.f + expf(-x)); }

// init: c state + bf16-split state S = [h0 | 0]
__global__ void init_kernel(const float* __restrict__ h0, const float* __restrict__ c0) {
    int i = blockIdx.x * 256 + threadIdx.x;    // 0..65535
    if (i < BB*DD) g_c[i] = c0[i];
    int b = i >> 11, k = i & (SD - 1);
    float v = (k < DD) ? h0[b * DD + k] : 0.f;
    __nv_bfloat16 h = __float2bfloat16(v);
    g_S_hi[i] = h;
    g_S_lo[i] = __float2bfloat16(v - __bfloat162float(h));
}

// ============================================================================
// tsplit<MODE>: transpose + hi/lo split, src fp32 [K'][N] -> [N][K] bf16
// 0: Wfc->WhiT  1: Wxa->WxaT  2: Wxe->WxeT  3: Wm->WmT  4: Wa->WaT
// 5: Wh -> WzT0 ([Wh^T ; 0] : rows k>=DD are zero)
// ============================================================================
template<int MODE>
__global__ void tsplit(const float* __restrict__ src, int K, int N)
{
    __nv_bfloat16* dhi; __nv_bfloat16* dlo;
    if (MODE == 0)      { dhi = g_WhiT;     dlo = g_WloT;     }
    else if (MODE == 1) { dhi = g_WxaT_hi;  dlo = g_WxaT_lo;  }
    else if (MODE == 2) { dhi = g_WxeT_hi;  dlo = g_WxeT_lo;  }
    else if (MODE == 3) { dhi = g_WmT_hi;   dlo = g_WmT_lo;   }
    else if (MODE == 4) { dhi = g_WaT_hi;   dlo = g_WaT_lo;   }
    else                { dhi = g_WzT0_hi;  dlo = g_WzT0_lo;  }

    __shared__ float tile[32][33];
    int n0 = blockIdx.x * 32, k0 = blockIdx.y * 32;
    int tx = threadIdx.x, ty = threadIdx.y;
#pragma unroll
    for (int i = 0; i < 4; i++) {
        int kk = k0 + ty + i*8;
        float v;
        if (MODE == 5) v = (kk < DD) ? src[(size_t)kk * N + n0 + tx] : 0.f;
        else           v = src[(size_t)kk * N + n0 + tx];
        tile[ty + i*8][tx] = v;
    }
    __syncthreads();
#pragma unroll
    for (int i = 0; i < 4; i++) {
        float v = tile[tx][ty + i*8];
        __nv_bfloat16 h = __float2bfloat16(v);
        size_t o = (size_t)(n0 + ty + i*8) * K + k0 + tx;
        dhi[o] = h;
        dlo[o] = __float2bfloat16(v - __bfloat162float(h));
    }
}

// rsplit<MODE>: element-wise hi/lo split. 0: Wa -> g_Wa. 1: memory -> g_mem.
template<int MODE>
__global__ void rsplit(const float* __restrict__ src)
{
    __nv_bfloat16* dhi = (MODE == 0) ? g_Wa_hi : g_mem_hi;
    __nv_bfloat16* dlo = (MODE == 0) ? g_Wa_lo : g_mem_lo;
    int i = blockIdx.x * 256 + threadIdx.x;
    float v = src[i];
    __nv_bfloat16 h = __float2bfloat16(v);
    dhi[i] = h;
    dlo[i] = __float2bfloat16(v - __bfloat162float(h));
}

// gathered embedding split
__global__ void split_emb(const float* __restrict__ emb, const int* __restrict__ ids) {
    int i = blockIdx.x * 256 + threadIdx.x;
    int m = i >> 8, k = i & 255;
    float v = 0.f;
    if (m < MROWS) v = emb[(size_t)ids[(m & 31) * TT + (m >> 5)] * EE + k];
    __nv_bfloat16 h = __float2bfloat16(v);
    g_emb_hi[i] = h;
    g_emb_lo[i] = __float2bfloat16(v - __bfloat162float(h));
}

// concat [hHist, ctxHist] split -> g_AX (pad rows zero)
__global__ void split_ax() {
    int i = blockIdx.x * 256 + threadIdx.x;
    int m = i >> 11, k = i & 2047;
    float v = 0.f;
    if (m < MROWS)
        v = (k < DD) ? g_hHist[(size_t)m * DD + k] : g_ctxHist[(size_t)m * DD + (k - DD)];
    __nv_bfloat16 h = __float2bfloat16(v);
    g_AX_hi[i] = h;
    g_AX_lo[i] = __float2bfloat16(v - __bfloat162float(h));
}

// ============================================================================
// shared MMA helpers
// ============================================================================
__device__ __forceinline__ uint32_t sw128(uint32_t x) { return x ^ ((x >> 3) & 0x70); }
__device__ __forceinline__ uint32_t smem_u32(const void* p) {
    uint32_t a;
    asm("{ .reg .u64 t; cvta.to.shared.u64 t, %1; cvt.u32.u64 %0, t; }" : "=r"(a) : "l"(p));
    return a;
}
__device__ __forceinline__ void cpa16(uint32_t dst, const __nv_bfloat16* src) {
    asm volatile("cp.async.cg.shared.global [%0], [%1], 16;"
                 :: "r"(dst), "l"(__cvta_generic_to_global(src)) : "memory");
}
__device__ __forceinline__ void ldsm4(uint32_t& r0, uint32_t& r1, uint32_t& r2, uint32_t& r3,
                                      uint32_t a) {
    asm volatile("ldmatrix.sync.aligned.m8n8.x4.shared.b16 {%0,%1,%2,%3}, [%4];"
                 : "=r"(r0), "=r"(r1), "=r"(r2), "=r"(r3) : "r"(a));
}
__device__ __forceinline__ void mma16816(float* c, const uint32_t* a, const uint32_t* b) {
    asm volatile("mma.sync.aligned.m16n8k16.row.col.f32.bf16.bf16.f32 "
                 "{%0,%1,%2,%3}, {%4,%5,%6,%7}, {%8,%9}, {%0,%1,%2,%3};"
                 : "+f"(c[0]), "+f"(c[1]), "+f"(c[2]), "+f"(c[3])
                 : "r"(a[0]), "r"(a[1]), "r"(a[2]), "r"(a[3]), "r"(b[0]), "r"(b[1]));
}

// ============================================================================
// zstep_mma: z partials = S[32,2048] @ WzT^T  (4-term split, fp32-exact class)
// grid (16 n-tiles of 256, NSPLIT k-splits of 256); 256 thr; 1 CTA/SM wave.
// ============================================================================
#define ZAB 4096
#define ZBB 32768
#define ZSTAGE (2*ZAB + 2*ZBB)
#define ZSMEM (2*ZSTAGE)

__device__ __forceinline__ void z_stage(uint32_t sb, const __nv_bfloat16* Bh_g,
                                        const __nv_bfloat16* Bl_g,
                                        int n0, int k0, int tid) {
#pragma unroll
    for (int i = 0; i < 2; i++) {                  // A: 512 cp
        int idx = tid + i * 256;
        int mat = idx >> 8, r = (idx >> 3) & 31, s = idx & 7;
        const __nv_bfloat16* base = mat ? g_S_lo : g_S_hi;
        cpa16(sb + mat * ZAB + sw128(r * 128 + s * 16),
              base + (size_t)r * SD + k0 + s * 8);
    }
#pragma unroll
    for (int i = 0; i < 16; i++) {                 // B: 4096 cp
        int idx = tid + i * 256;
        int mat = idx >> 11, r = (idx >> 3) & 255, s = idx & 7;
        const __nv_bfloat16* base = mat ? Bl_g : Bh_g;
        cpa16(sb + 2*ZAB + mat * ZBB + sw128(r * 128 + s * 16),
              base + (size_t)(n0 + r) * SD + k0 + s * 8);
    }
    asm volatile("cp.async.commit_group;" ::: "memory");
}

__global__ __launch_bounds__(256)
void zstep_mma(int t)
{
    const __nv_bfloat16* Bh_g = (t == 0) ? g_WzT0_hi : g_WzT_hi;
    const __nv_bfloat16* Bl_g = (t == 0) ? g_WzT0_lo : g_WzT_lo;

    extern __shared__ char dsm[];
    const uint32_t sb0 = smem_u32(dsm);
    const int tid = threadIdx.x, wid = tid >> 5, lane = tid & 31;
    const int n0 = blockIdx.x * 256;
    const int kb = blockIdx.y * (SD / NSPLIT);     // 256 per split

    float acc[2][4][4];
#pragma unroll
    for (int i = 0; i < 2; i++)
#pragma unroll
        for (int j = 0; j < 4; j++)
#pragma unroll
            for (int k = 0; k < 4; k++) acc[i][j][k] = 0.f;

    z_stage(sb0, Bh_g, Bl_g, n0, kb, tid);

    const int NCH = (SD / NSPLIT) / 64;            // 4
    for (int ch = 0; ch < NCH; ch++) {
        const uint32_t cb = sb0 + (ch & 1) * ZSTAGE;
        asm volatile("cp.async.wait_group 0;" ::: "memory");
        __syncthreads();
        if (ch + 1 < NCH)
            z_stage(sb0 + ((ch + 1) & 1) * ZSTAGE, Bh_g, Bl_g, n0, kb + (ch + 1) * 64, tid);

        const uint32_t Ah = cb, Al = cb + ZAB, Bh = cb + 2*ZAB, Bl = cb + 2*ZAB + ZBB;
#pragma unroll
        for (int ks = 0; ks < 4; ks++) {
            const int kcol = ks * 32;
            uint32_t ahi[2][4], alo[2][4];
#pragma unroll
            for (int mf = 0; mf < 2; mf++) {
                uint32_t off = sw128((mf*16 + (lane & 15)) * 128 + kcol + (lane >> 4) * 16);
                ldsm4(ahi[mf][0], ahi[mf][1], ahi[mf][2], ahi[mf][3], Ah + off);
                ldsm4(alo[mf][0], alo[mf][1], alo[mf][2], alo[mf][3], Al + off);
            }
            uint32_t bhi[4][2], blo[4][2];
#pragma unroll
            for (int p = 0; p < 2; p++) {
                int q = lane >> 3;
                uint32_t off = sw128((wid*32 + p*16 + ((q >> 1) & 1)*8 + (lane & 7)) * 128
                                     + kcol + (q & 1) * 16);
                ldsm4(bhi[2*p][0], bhi[2*p][1], bhi[2*p+1][0], bhi[2*p+1][1], Bh + off);
                ldsm4(blo[2*p][0], blo[2*p][1], blo[2*p+1][0], blo[2*p+1][1], Bl + off);
            }
#pragma unroll
            for (int mf = 0; mf < 2; mf++)
#pragma unroll
                for (int nf = 0; nf < 4; nf++) {
                    mma16816(acc[mf][nf], ahi[mf], bhi[nf]);
                    mma16816(acc[mf][nf], ahi[mf], blo[nf]);
                    mma16816(acc[mf][nf], alo[mf], bhi[nf]);
                    mma16816(acc[mf][nf], alo[mf], blo[nf]);
                }
        }
        __syncthreads();
    }

    // epilogue -> zpart[(split*32 + b)][n]
    float* zp = g_zpart + (size_t)(blockIdx.y * BB) * NZ;
#pragma unroll
    for (int mf = 0; mf < 2; mf++) {
#pragma unroll
        for (int half = 0; half < 2; half++) {
            int m = mf*16 + (lane >> 2) + half*8;
#pragma unroll
            for (int nf = 0; nf < 4; nf++) {
                int n = n0 + wid*32 + nf*8 + (lane & 3)*2;
                float2 v;
                v.x = acc[mf][nf][half*2 + 0];
                v.y = acc[mf][nf][half*2 + 1];
                *(float2*)&zp[(size_t)m * NZ + n] = v;
            }
        }
    }
}

// ============================================================================
// step_fused: z-combine + LSTM gates + scores + softmax + context (+S split)
// ============================================================================
#define ACC2(v, p) { float2 _t = *(const float2*)(p); v.x += _t.x; v.y += _t.y; }

__global__ __launch_bounds__(512)
void step_fused(const float* __restrict__ b4, const float* __restrict__ scale,
                const float* __restrict__ memory, int t)
{
    __shared__ __align__(16) float h_s[DD];
    __shared__ float sc[TIN_];
    __shared__ float al_s[TIN_];
    const int b = blockIdx.x, tid = threadIdx.x;
    const int j0 = tid * 2;

    float2 zi = *(const float2*)(b4 + j0);
    float2 zf = *(const float2*)(b4 + DD + j0);
    float2 zg = *(const float2*)(b4 + 2*DD + j0);
    float2 zo = *(const float2*)(b4 + 3*DD + j0);
    const float* ew = g_embW + ((size_t)t*BB + b) * NZ;
    ACC2(zi, ew + j0); ACC2(zf, ew + DD + j0); ACC2(zg, ew + 2*DD + j0); ACC2(zo, ew + 3*DD + j0);
#pragma unroll
    for (int s = 0; s < NSPLIT; s++) {
        const float* zp = g_zpart + (size_t)(s*BB + b) * NZ;
        ACC2(zi, zp + j0); ACC2(zf, zp + DD + j0);
        ACC2(zg, zp + 2*DD + j0); ACC2(zo, zp + 3*DD + j0);
    }
    float2 c = *(const float2*)(g_c + b*DD + j0);
    float2 cn, hn;
    cn.x = sigm(zf.x) * c.x + sigm(zi.x) * tanhf(zg.x);
    cn.y = sigm(zf.y) * c.y + sigm(zi.y) * tanhf(zg.y);
    hn.x = sigm(zo.x) * tanhf(cn.x);
    hn.y = sigm(zo.y) * tanhf(cn.y);
    *(float2*)(g_c + b*DD + j0) = cn;
    *(float2*)(g_hHist + ((size_t)t*BB + b)*DD + j0) = hn;
    *(float2*)(h_s + j0) = hn;
    // state split (h part)
    {
        __nv_bfloat16 hx = __float2bfloat16(hn.x);
        __nv_bfloat16 hy = __float2bfloat16(hn.y);
        g_S_hi[b*SD + j0]     = hx;
        g_S_hi[b*SD + j0 + 1] = hy;
        g_S_lo[b*SD + j0]     = __float2bfloat16(hn.x - __bfloat162float(hx));
        g_S_lo[b*SD + j0 + 1] = __float2bfloat16(hn.y - __bfloat162float(hy));
    }
    __syncthreads();

    const int w = tid >> 5, lane = tid & 31;
    const float4* hv4 = (const float4*)h_s;
    float4 hreg[8];
#pragma unroll
    for (int it = 0; it < 8; it++) hreg[it] = hv4[it*32 + lane];
    const float sc0 = scale[0];
    float pa[4] = {0.f, 0.f, 0.f, 0.f};
#pragma unroll
    for (int p = 0; p < 4; p++) {
        const float4* kr = (const float4*)(g_keys + ((size_t)b*TIN_ + w*4 + p) * DD);
#pragma unroll
        for (int it = 0; it < 8; it++) {
            float4 kv = kr[it*32 + lane];
            pa[p] += kv.x*hreg[it].x + kv.y*hreg[it].y + kv.z*hreg[it].z + kv.w*hreg[it].w;
        }
    }
#pragma unroll
    for (int p = 0; p < 4; p++) {
        float v = pa[p];
#pragma unroll
        for (int off = 16; off > 0; off >>= 1)
            v += __shfl_xor_sync(0xffffffffu, v, off);
        if (lane == 0) sc[w*4 + p] = v * sc0;
    }
    __syncthreads();

    if (tid < 32) {
        float a = sc[tid], c2 = sc[tid + 32];
        float mx = fmaxf(a, c2);
#pragma unroll
        for (int off = 16; off > 0; off >>= 1)
            mx = fmaxf(mx, __shfl_xor_sync(0xffffffffu, mx, off));
        float ea = expf(a - mx), eb = expf(c2 - mx);
        float ssum = ea + eb;
#pragma unroll
        for (int off = 16; off > 0; off >>= 1)
            ssum += __shfl_xor_sync(0xffffffffu, ssum, off);
        float inv = 1.f / ssum;
        al_s[tid] = ea * inv;
        al_s[tid + 32] = eb * inv;
    }
    __syncthreads();

    const float* mb = memory + (size_t)b * TIN_ * DD;
    float* ch = g_ctxHist + ((size_t)t*BB + b) * DD;
#pragma unroll
    for (int q = 0; q < 2; q++) {
        int d = tid + q * 512;
        float acc = 0.f;
#pragma unroll 8
        for (int tt2 = 0; tt2 < TIN_; tt2++)
            acc += al_s[tt2] * mb[(size_t)tt2 * DD + d];
        ch[d] = acc;
        // state split (ctx part)
        __nv_bfloat16 hh = __float2bfloat16(acc);
        g_S_hi[b*SD + DD + d] = hh;
        g_S_lo[b*SD + DD + d] = __float2bfloat16(acc - __bfloat162float(hh));
    }
}

// ============================================================================
// mma_gemm<EPI>: bf16-split GEMM. Operands selected device-side.
// 0: logits (3-term, bias+permute -> outp)      2: keys -> g_keys (4-term)
// 3: embW -> g_embW (4-term)                    4: attnAll -> g_Ahi/g_Alo split
// 5: WzT = WxaT@Wa (+WzT0) -> g_WzT hi/lo split (4-term)
// ============================================================================
#define LMATB 16384
#define LSTAGE (4*LMATB)
#define LSMEM (2*LSTAGE)

__device__ __forceinline__ void lm_stage(uint32_t sb, const __nv_bfloat16* Ahi,
                                         const __nv_bfloat16* Alo,
                                         const __nv_bfloat16* Bhi,
                                         const __nv_bfloat16* Blo,
                                         int m0, int n0, int k0, int K, int tid) {
#pragma unroll
    for (int i = 0; i < 16; i++) {
        int idx = tid + i * 256;
        int mat = idx >> 10;
        int r   = (idx >> 3) & 127;
        int s   = idx & 7;
        const __nv_bfloat16* base =
            (mat == 0) ? Ahi : (mat == 1) ? Alo : (mat == 2) ? Bhi : Blo;
        int rowg = ((mat < 2) ? m0 : n0) + r;
        cpa16(sb + mat * LMATB + sw128(r * 128 + s * 16),
              base + (size_t)rowg * K + k0 + s * 8);
    }
    asm volatile("cp.async.commit_group;" ::: "memory");
}

template<int EPI>
__global__ __launch_bounds__(256)
void mma_gemm(const float* __restrict__ aux, float* __restrict__ outp, int K, int N)
{
    const __nv_bfloat16 *Ahi, *Alo, *Bhi, *Blo;
    float* dst = outp;
    if (EPI == 0)      { Ahi = g_Ahi;     Alo = g_Alo;     Bhi = g_WhiT;    Blo = g_WloT;    }
    else if (EPI == 2) { Ahi = g_mem_hi;  Alo = g_mem_lo;  Bhi = g_WmT_hi;  Blo = g_WmT_lo;  dst = g_keys; }
    else if (EPI == 3) { Ahi = g_emb_hi;  Alo = g_emb_lo;  Bhi = g_WxeT_hi; Blo = g_WxeT_lo; dst = g_embW; }
    else if (EPI == 4) { Ahi = g_AX_hi;   Alo = g_AX_lo;   Bhi = g_WaT_hi;  Blo = g_WaT_lo;  }
    else               { Ahi = g_WxaT_hi; Alo = g_WxaT_lo; Bhi = g_Wa_hi;   Blo = g_Wa_lo;   }

    extern __shared__ char dsm[];
    const uint32_t sb0 = smem_u32(dsm);
    const int tid = threadIdx.x, wid = tid >> 5, lane = tid & 31;
    const int m0 = blockIdx.x * 128, n0 = blockIdx.y * 128;
    const int wm = wid >> 2, wn = wid & 3;

    float acc[4][4][4];
#pragma unroll
    for (int i = 0; i < 4; i++)
#pragma unroll
        for (int j = 0; j < 4; j++)
#pragma unroll
            for (int k = 0; k < 4; k++) acc[i][j][k] = 0.f;

    lm_stage(sb0, Ahi, Alo, Bhi, Blo, m0, n0, 0, K, tid);

    const int NCH = K / 64;
    for (int ch = 0; ch < NCH; ch++) {
        const uint32_t cb = sb0 + (ch & 1) * LSTAGE;
        asm volatile("cp.async.wait_group 0;" ::: "memory");
        __syncthreads();
        if (ch + 1 < NCH)
            lm_stage(sb0 + ((ch + 1) & 1) * LSTAGE, Ahi, Alo, Bhi, Blo,
                     m0, n0, (ch + 1) * 64, K, tid);

        const uint32_t Ah = cb, Al = cb + LMATB, Bh = cb + 2*LMATB, Bl = cb + 3*LMATB;
#pragma unroll
        for (int ks = 0; ks < 4; ks++) {
            const int kb = ks * 32;
            uint32_t ahi[4][4], alo[4][4];
#pragma unroll
            for (int mf = 0; mf < 4; mf++) {
                uint32_t off = sw128((wm*64 + mf*16 + (lane & 15)) * 128
                                     + kb + (lane >> 4) * 16);
                ldsm4(ahi[mf][0], ahi[mf][1], ahi[mf][2], ahi[mf][3], Ah + off);
                ldsm4(alo[mf][0], alo[mf][1], alo[mf][2], alo[mf][3], Al + off);
            }
            uint32_t bhi[4][2], blo[4][2];
#pragma unroll
            for (int p = 0; p < 2; p++) {
                int q = lane >> 3;
                uint32_t off = sw128((wn*32 + p*16 + ((q >> 1) & 1)*8 + (lane & 7)) * 128
                                     + kb + (q & 1) * 16);
                ldsm4(bhi[2*p][0], bhi[2*p][1], bhi[2*p+1][0], bhi[2*p+1][1], Bh + off);
                ldsm4(blo[2*p][0], blo[2*p][1], blo[2*p+1][0], blo[2*p+1][1], Bl + off);
            }
#pragma unroll
            for (int mf = 0; mf < 4; mf++)
#pragma unroll
                for (int nf = 0; nf < 4; nf++) {
                    mma16816(acc[mf][nf], ahi[mf], bhi[nf]);
                    mma16816(acc[mf][nf], ahi[mf], blo[nf]);
                    mma16816(acc[mf][nf], alo[mf], bhi[nf]);
                    if (EPI != 0) mma16816(acc[mf][nf], alo[mf], blo[nf]);
                }
        }
        __syncthreads();
    }

    if (EPI == 0) {
        float2 bias[4];
#pragma unroll
        for (int nf = 0; nf < 4; nf++)
            bias[nf] = *(const float2*)&aux[n0 + wn*32 + nf*8 + (lane & 3)*2];
#pragma unroll
        for (int mf = 0; mf < 4; mf++) {
#pragma unroll
            for (int half = 0; half < 2; half++) {
                int m = m0 + wm*64 + mf*16 + (lane >> 2) + half*8;
                if (m < MROWS) {
                    float* orow = dst + ((size_t)(m & 31) * TT + (m >> 5)) * VV;
#pragma unroll
                    for (int nf = 0; nf < 4; nf++) {
                        int n = n0 + wn*32 + nf*8 + (lane & 3)*2;
                        float2 v;
                        v.x = acc[mf][nf][half*2 + 0] + bias[nf].x;
                        v.y = acc[mf][nf][half*2 + 1] + bias[nf].y;
                        *(float2*)&orow[n] = v;
                    }
                }
            }
        }
    } else {
#pragma unroll
        for (int mf = 0; mf < 4; mf++) {
#pragma unroll
            for (int half = 0; half < 2; half++) {
                int m = m0 + wm*64 + mf*16 + (lane >> 2) + half*8;
#pragma unroll
                for (int nf = 0; nf < 4; nf++) {
                    int n = n0 + wn*32 + nf*8 + (lane & 3)*2;
                    float2 v;
                    v.x = acc[mf][nf][half*2 + 0];
                    v.y = acc[mf][nf][half*2 + 1];
                    size_t o = (size_t)m * N + n;
                    if (EPI == 5) {
                        v.x += __bfloat162float(g_WzT0_hi[o])   + __bfloat162float(g_WzT0_lo[o]);
                        v.y += __bfloat162float(g_WzT0_hi[o+1]) + __bfloat162float(g_WzT0_lo[o+1]);
                        __nv_bfloat16 hx = __float2bfloat16(v.x);
                        __nv_bfloat16 hy = __float2bfloat16(v.y);
                        g_WzT_hi[o]     = hx;
                        g_WzT_hi[o + 1] = hy;
                        g_WzT_lo[o]     = __float2bfloat16(v.x - __bfloat162float(hx));
                        g_WzT_lo[o + 1] = __float2bfloat16(v.y - __bfloat162float(hy));
                    } else if (EPI == 4) {
                        __nv_bfloat16 hx = __float2bfloat16(v.x);
                        __nv_bfloat16 hy = __float2bfloat16(v.y);
                        g_Ahi[o]     = hx;
                        g_Ahi[o + 1] = hy;
                        g_Alo[o]     = __float2bfloat16(v.x - __bfloat162float(hx));
                        g_Alo[o + 1] = __float2bfloat16(v.y - __bfloat162float(hy));
                    } else {
                        *(float2*)&dst[o] = v;
                    }
                }
            }
        }
    }
}

extern "C" void kernel_launch(void* const* d_in, const int* in_sizes, int n_in,
                              void* d_out, int out_size) {
    const int*   ids    = (const int*)  d_in[0];
    const float* h0     = (const float*)d_in[1];
    const float* c0     = (const float*)d_in[2];
    const float* memory = (const float*)d_in[3];
    const float* emb    = (const float*)d_in[4];
    const float* Wx     = (const float*)d_in[5];
    const float* Wh     = (const float*)d_in[6];
    const float* b4     = (const float*)d_in[7];
    const float* Wm     = (const float*)d_in[8];
    const float* scale  = (const float*)d_in[9];
    const float* Wa     = (const float*)d_in[10];
    const float* Wfc    = (const float*)d_in[11];
    const float* bfc    = (const float*)d_in[12];
    float* out = (float*)d_out;

    cudaFuncSetAttribute(mma_gemm<0>, cudaFuncAttributeMaxDynamicSharedMemorySize, LSMEM);
    cudaFuncSetAttribute(mma_gemm<2>, cudaFuncAttributeMaxDynamicSharedMemorySize, LSMEM);
    cudaFuncSetAttribute(mma_gemm<3>, cudaFuncAttributeMaxDynamicSharedMemorySize, LSMEM);
    cudaFuncSetAttribute(mma_gemm<4>, cudaFuncAttributeMaxDynamicSharedMemorySize, LSMEM);
    cudaFuncSetAttribute(mma_gemm<5>, cudaFuncAttributeMaxDynamicSharedMemorySize, LSMEM);
    cudaFuncSetAttribute(zstep_mma,   cudaFuncAttributeMaxDynamicSharedMemorySize, ZSMEM);

    init_kernel<<<256, 256>>>(h0, c0);

    // ---- one-time operand prep ----
    tsplit<0><<<dim3(VV/32, DD/32),   dim3(32,8)>>>(Wfc, DD, VV);
    tsplit<1><<<dim3(NZ/32, DD/32),   dim3(32,8)>>>(Wx + (size_t)EE*NZ, DD, NZ);
    tsplit<2><<<dim3(NZ/32, EE/32),   dim3(32,8)>>>(Wx, EE, NZ);
    tsplit<3><<<dim3(DD/32, DD/32),   dim3(32,8)>>>(Wm, DD, DD);
    tsplit<4><<<dim3(DD/32, 2*DD/32), dim3(32,8)>>>(Wa, 2*DD, DD);
    tsplit<5><<<dim3(NZ/32, SD/32),   dim3(32,8)>>>(Wh, SD, NZ);     // WzT0 = [Wh^T ; 0]
    rsplit<0><<<(2*DD*DD)/256, 256>>>(Wa);
    rsplit<1><<<(MPAD*DD)/256, 256>>>(memory);
    split_emb<<<(MPAD*EE)/256, 256>>>(emb, ids);

    // keys = memory @ Wm
    mma_gemm<2><<<dim3(16, 8), 256, LSMEM>>>(nullptr, nullptr, DD, DD);
    // WzT = WxaT @ Wa^T (+WzT0), split -> g_WzT
    mma_gemm<5><<<dim3(32, 16), 256, LSMEM>>>(nullptr, nullptr, DD, SD);
    // embW = emb[ids] @ Wx_emb
    mma_gemm<3><<<dim3(16, 32), 256, LSMEM>>>(nullptr, nullptr, EE, NZ);

    for (int t = 0; t < TT; t++) {
        zstep_mma<<<dim3(16, NSPLIT), 256, ZSMEM>>>(t);
        step_fused<<<BB, 512>>>(b4, scale, memory, t);
    }

    // attnAll = [hHist,ctxHist] @ Wa -> bf16 hi/lo directly
    split_ax<<<(MPAD*2*DD)/256, 256>>>();
    mma_gemm<4><<<dim3(16, 8), 256, LSMEM>>>(nullptr, nullptr, 2*DD, DD);
    // logits = attnAll @ Wfc + bfc
    mma_gemm<0><<<dim3(16, 250), 256, LSMEM>>>(bfc, out, DD, VV);
}